// round 1
// baseline (speedup 1.0000x reference)
#include <cuda_runtime.h>
#include <cstdint>

// Problem constants
#define B_   4
#define SEQ  2048
#define DM   512
#define NH   8
#define HD   64

// Scratch (device globals — no allocation allowed in kernel_launch)
__device__ float g_Qh[B_ * SEQ * DM];
__device__ float g_Kh[B_ * SEQ * DM];
__device__ float g_Vh[B_ * SEQ * DM];
__device__ float g_Av[B_ * SEQ * DM];

// ---------------------------------------------------------------------------
// GEMM (NT): C[M,N] = A[M,512] * W[N,512]^T
// Both A and W are K-major (K = 512 contiguous). Block tile 128x64, KT=16,
// 256 threads, 8x4 micro-tile per thread.
// ---------------------------------------------------------------------------
__global__ __launch_bounds__(256) void gemm_nt_kernel(
    const float* __restrict__ A, const float* __restrict__ W,
    float* __restrict__ C, int M, int N)
{
    __shared__ float As[128][16];   // natural [m][k]
    __shared__ float BsT[16][68];   // transposed [k][n], pad 68 keeps float4 align

    const int tid = threadIdx.x;
    const int tx = tid & 15;        // n direction (4 cols each)
    const int ty = tid >> 4;        // m direction (8 rows each)
    const int m0 = blockIdx.y * 128;
    const int n0 = blockIdx.x * 64;
    const int lk = tid & 15;
    const int lr = tid >> 4;

    float acc[8][4];
#pragma unroll
    for (int i = 0; i < 8; i++)
#pragma unroll
        for (int j = 0; j < 4; j++) acc[i][j] = 0.f;

    for (int k0 = 0; k0 < DM; k0 += 16) {
#pragma unroll
        for (int r = 0; r < 8; r++)
            As[lr + 16 * r][lk] = A[(size_t)(m0 + lr + 16 * r) * DM + k0 + lk];
#pragma unroll
        for (int r = 0; r < 4; r++)
            BsT[lk][lr + 16 * r] = W[(size_t)(n0 + lr + 16 * r) * DM + k0 + lk];
        __syncthreads();

#pragma unroll
        for (int kk = 0; kk < 16; kk++) {
            float4 b4 = *(const float4*)&BsT[kk][tx * 4];
            float bv[4] = {b4.x, b4.y, b4.z, b4.w};
#pragma unroll
            for (int i = 0; i < 8; i++) {
                float a = As[ty * 8 + i][kk];
#pragma unroll
                for (int j = 0; j < 4; j++)
                    acc[i][j] = fmaf(a, bv[j], acc[i][j]);
            }
        }
        __syncthreads();
    }

#pragma unroll
    for (int i = 0; i < 8; i++) {
        float4 ov = {acc[i][0], acc[i][1], acc[i][2], acc[i][3]};
        *(float4*)&C[(size_t)(m0 + ty * 8 + i) * N + n0 + tx * 4] = ov;
    }
}

// ---------------------------------------------------------------------------
// Flash attention: per block (q-tile of 128 rows, head h, batch b).
// KV tiles of 64. Online softmax with per-key mask (-1e30).
// Heads are slices of g_Qh/g_Kh/g_Vh: col offset h*64 within the 512-wide row.
// ---------------------------------------------------------------------------
#define QT 128
#define KVT 64

// smem layout (floats): QsT[64][132], KsT[64][68], Vs[64][64], Ps[128][64]
#define SM_QST 0
#define SM_KST (64 * 132)
#define SM_VS  (SM_KST + 64 * 68)
#define SM_PS  (SM_VS + 64 * 64)
#define SM_TOTAL_FLOATS (SM_PS + 128 * 64)

extern __shared__ float fa_smem[];

__global__ __launch_bounds__(256) void flash_attn_kernel(const int* __restrict__ mask)
{
    float* QsT = fa_smem + SM_QST;   // [kk][r], stride 132, pre-scaled
    float* KsT = fa_smem + SM_KST;   // [kk][c], stride 68
    float* Vs  = fa_smem + SM_VS;    // [j][c],  stride 64
    float* Ps  = fa_smem + SM_PS;    // [r][j],  stride 64

    const int tid = threadIdx.x;
    const int tx = tid & 15;         // kv-col / out-col direction (4 each)
    const int ty = tid >> 4;         // q-row direction (8 each)
    const int q0 = blockIdx.x * QT;
    const int h  = blockIdx.y;
    const int b  = blockIdx.z;
    const float scale = 0.125f;      // 1/sqrt(64)

    // Load Q tile, transposed + pre-scaled (loaded once per block)
    {
        const int kk = tid & 63;
        const int rb = (tid >> 6) * 32;
#pragma unroll 8
        for (int u = 0; u < 32; u++) {
            int r = rb + u;
            QsT[kk * 132 + r] =
                scale * g_Qh[(size_t)(b * SEQ + q0 + r) * DM + h * HD + kk];
        }
    }

    float o[8][4];
    float mrow[8], lrow[8];
#pragma unroll
    for (int i = 0; i < 8; i++) {
        mrow[i] = -3.0e38f;
        lrow[i] = 0.f;
#pragma unroll
        for (int j = 0; j < 4; j++) o[i][j] = 0.f;
    }

    const int* mptr = mask + b * SEQ;

    for (int kv0 = 0; kv0 < SEQ; kv0 += KVT) {
        __syncthreads();   // protect Ps/Vs of previous iteration
        // Load K (transposed) and V (natural) tiles
        {
            const int kk = tid & 63;
            const int cb = (tid >> 6) * 16;
#pragma unroll 4
            for (int u = 0; u < 16; u++) {
                int c = cb + u;
                KsT[kk * 68 + c] =
                    g_Kh[(size_t)(b * SEQ + kv0 + c) * DM + h * HD + kk];
            }
            const int c4 = (tid & 15) * 4;
            const int jb = tid >> 4;
#pragma unroll
            for (int u = 0; u < 4; u++) {
                int j = jb + 16 * u;
                *(float4*)&Vs[j * 64 + c4] =
                    *(const float4*)&g_Vh[(size_t)(b * SEQ + kv0 + j) * DM + h * HD + c4];
            }
        }
        __syncthreads();

        // S = (Q*scale) K^T   (s[i][j]: row q0+ty*8+i, col kv0+tx*4+j)
        float s[8][4];
#pragma unroll
        for (int i = 0; i < 8; i++)
#pragma unroll
            for (int j = 0; j < 4; j++) s[i][j] = 0.f;

#pragma unroll 4
        for (int kk = 0; kk < HD; kk++) {
            float4 k4 = *(const float4*)&KsT[kk * 68 + tx * 4];
            float kb[4] = {k4.x, k4.y, k4.z, k4.w};
            float4 qa = *(const float4*)&QsT[kk * 132 + ty * 8];
            float4 qb = *(const float4*)&QsT[kk * 132 + ty * 8 + 4];
            float qv[8] = {qa.x, qa.y, qa.z, qa.w, qb.x, qb.y, qb.z, qb.w};
#pragma unroll
            for (int i = 0; i < 8; i++)
#pragma unroll
                for (int j = 0; j < 4; j++)
                    s[i][j] = fmaf(qv[i], kb[j], s[i][j]);
        }

        // Mask (per key): attn_mask == 0 -> -1e30 (matches reference exactly)
        {
            int4 mk = *(const int4*)&mptr[kv0 + tx * 4];
            int mv[4] = {mk.x, mk.y, mk.z, mk.w};
#pragma unroll
            for (int j = 0; j < 4; j++)
                if (mv[j] == 0)
#pragma unroll
                    for (int i = 0; i < 8; i++) s[i][j] = -1.0e30f;
        }

        // Online softmax (rows shared across the 16 lanes with equal ty)
#pragma unroll
        for (int i = 0; i < 8; i++) {
            float mx = fmaxf(fmaxf(s[i][0], s[i][1]), fmaxf(s[i][2], s[i][3]));
            mx = fmaxf(mx, __shfl_xor_sync(0xffffffffu, mx, 1));
            mx = fmaxf(mx, __shfl_xor_sync(0xffffffffu, mx, 2));
            mx = fmaxf(mx, __shfl_xor_sync(0xffffffffu, mx, 4));
            mx = fmaxf(mx, __shfl_xor_sync(0xffffffffu, mx, 8));
            float mnew = fmaxf(mrow[i], mx);
            float alpha = __expf(mrow[i] - mnew);
            float rs = 0.f;
#pragma unroll
            for (int j = 0; j < 4; j++) {
                float p = __expf(s[i][j] - mnew);
                s[i][j] = p;
                rs += p;
            }
            rs += __shfl_xor_sync(0xffffffffu, rs, 1);
            rs += __shfl_xor_sync(0xffffffffu, rs, 2);
            rs += __shfl_xor_sync(0xffffffffu, rs, 4);
            rs += __shfl_xor_sync(0xffffffffu, rs, 8);
            lrow[i] = lrow[i] * alpha + rs;
            mrow[i] = mnew;
#pragma unroll
            for (int j = 0; j < 4; j++) o[i][j] *= alpha;
#pragma unroll
            for (int j = 0; j < 4; j++)
                Ps[(ty * 8 + i) * 64 + tx * 4 + j] = s[i][j];
        }
        __syncthreads();

        // O += P V
#pragma unroll 4
        for (int jkv = 0; jkv < KVT; jkv++) {
            float4 v4 = *(const float4*)&Vs[jkv * 64 + tx * 4];
            float vb[4] = {v4.x, v4.y, v4.z, v4.w};
#pragma unroll
            for (int i = 0; i < 8; i++) {
                float p = Ps[(ty * 8 + i) * 64 + jkv];
#pragma unroll
                for (int j = 0; j < 4; j++)
                    o[i][j] = fmaf(p, vb[j], o[i][j]);
            }
        }
    }

    // Epilogue: normalize and store attn_vec slice
#pragma unroll
    for (int i = 0; i < 8; i++) {
        float inv = 1.f / lrow[i];
        float4 ov = {o[i][0] * inv, o[i][1] * inv, o[i][2] * inv, o[i][3] * inv};
        *(float4*)&g_Av[(size_t)(b * SEQ + q0 + ty * 8 + i) * DM + h * HD + tx * 4] = ov;
    }
}

// ---------------------------------------------------------------------------
// Launch
// ---------------------------------------------------------------------------
extern "C" void kernel_launch(void* const* d_in, const int* in_sizes, int n_in,
                              void* d_out, int out_size)
{
    const float* query = (const float*)d_in[0];
    const float* key_  = (const float*)d_in[1];
    const float* value = (const float*)d_in[2];
    const float* Wq    = (const float*)d_in[3];
    const float* Wk    = (const float*)d_in[4];
    const float* Wv    = (const float*)d_in[5];
    const float* Wo    = (const float*)d_in[6];
    const int*   mask  = (const int*)d_in[7];
    float* out = (float*)d_out;

    float *Qh, *Kh, *Vh, *Av;
    cudaGetSymbolAddress((void**)&Qh, g_Qh);
    cudaGetSymbolAddress((void**)&Kh, g_Kh);
    cudaGetSymbolAddress((void**)&Vh, g_Vh);
    cudaGetSymbolAddress((void**)&Av, g_Av);

    const int M = B_ * SEQ;  // 8192

    dim3 gGrid(DM / 64, M / 128);   // (8, 64)
    dim3 gBlk(256);

    // Projections
    gemm_nt_kernel<<<gGrid, gBlk>>>(query, Wq, Qh, M, DM);
    gemm_nt_kernel<<<gGrid, gBlk>>>(key_,  Wk, Kh, M, DM);
    gemm_nt_kernel<<<gGrid, gBlk>>>(value, Wv, Vh, M, DM);

    // Attention (flash, fused softmax + mask)
    static_assert(SM_TOTAL_FLOATS * 4 == 100352, "smem layout");
    cudaFuncSetAttribute(flash_attn_kernel,
                         cudaFuncAttributeMaxDynamicSharedMemorySize,
                         SM_TOTAL_FLOATS * 4);
    dim3 fGrid(SEQ / QT, NH, B_);   // (16, 8, 4)
    flash_attn_kernel<<<fGrid, 256, SM_TOTAL_FLOATS * 4>>>(mask);

    // Output projection
    gemm_nt_kernel<<<gGrid, gBlk>>>(Av, Wo, out, M, DM);
}

// round 4
// speedup vs baseline: 1.7101x; 1.7101x over previous
#include <cuda_runtime.h>
#include <cuda_bf16.h>
#include <cstdint>

// Problem constants
#define B_   4
#define SEQ  2048
#define DM   512
#define NH   8
#define HD   64

// Scratch (device globals — no allocation allowed in kernel_launch)
__device__ float g_Qh[B_ * SEQ * DM];
__device__ float g_Kh[B_ * SEQ * DM];
__device__ float g_Vh[B_ * SEQ * DM];
__device__ float g_Av[B_ * SEQ * DM];

// ---------------------------------------------------------------------------
// bf16 split helpers: x = hi + lo, hi = bf16(x), lo = bf16(x - hi).
// Packed bf16x2: element k in LOWER half, k+1 in UPPER half.
// ---------------------------------------------------------------------------
__device__ __forceinline__ void split2(float x0, float x1,
                                       uint32_t& hp, uint32_t& lp) {
    float h0 = __bfloat162float(__float2bfloat16_rn(x0));
    float h1 = __bfloat162float(__float2bfloat16_rn(x1));
    asm("cvt.rn.bf16x2.f32 %0, %1, %2;" : "=r"(hp) : "f"(h1), "f"(h0));
    asm("cvt.rn.bf16x2.f32 %0, %1, %2;" : "=r"(lp) : "f"(x1 - h1), "f"(x0 - h0));
}

// D += A(16x16) * B(16x8), bf16 in, fp32 accum. (g = lane>>2, tg = lane&3)
//  A: a0(g, 2tg:2tg+1) a1(g+8, 2tg:2tg+1) a2(g, 2tg+8:+9) a3(g+8, 2tg+8:+9)
//  B: b0(k=2tg:2tg+1, n=g) b1(k=2tg+8:+9, n=g)
//  C: c0(g,2tg) c1(g,2tg+1) c2(g+8,2tg) c3(g+8,2tg+1)
__device__ __forceinline__ void mmabf(float* d, const uint32_t* a, const uint32_t* b) {
    asm volatile(
        "mma.sync.aligned.m16n8k16.row.col.f32.bf16.bf16.f32 "
        "{%0,%1,%2,%3}, {%4,%5,%6,%7}, {%8,%9}, {%0,%1,%2,%3};"
        : "+f"(d[0]), "+f"(d[1]), "+f"(d[2]), "+f"(d[3])
        : "r"(a[0]), "r"(a[1]), "r"(a[2]), "r"(a[3]), "r"(b[0]), "r"(b[1]));
}

// ---------------------------------------------------------------------------
// Projection GEMM (NT, bf16x3): C[M,512] = A[M,512] * W[512,512]^T
// Block 128x64, BK=32 (2 k16 chunks), 8 warps 4(m)x2(n), warp tile 32x32.
// smem strides in u32: 20 (== 4 mod 32 -> conflict-free fragment loads).
// ---------------------------------------------------------------------------
__global__ __launch_bounds__(256) void gemm_bf3(
    const float* __restrict__ A, const float* __restrict__ W,
    float* __restrict__ C, int M)
{
    __shared__ uint32_t AsH[128 * 20], AsL[128 * 20];
    __shared__ uint32_t WsH[64 * 20],  WsL[64 * 20];

    const int tid = threadIdx.x, lane = tid & 31, warp = tid >> 5;
    const int g = lane >> 2, tg = lane & 3;
    const int m0 = blockIdx.y * 128, n0 = blockIdx.x * 64;
    const int wm = (warp >> 1) * 32, wn = (warp & 1) * 32;

    float acc[2][4][4];
#pragma unroll
    for (int mt = 0; mt < 2; mt++)
#pragma unroll
        for (int nt = 0; nt < 4; nt++)
#pragma unroll
            for (int j = 0; j < 4; j++) acc[mt][nt][j] = 0.f;

    const int srow = tid >> 3, scol = (tid & 7) * 4;   // 32 rows x 8 float4

    for (int k0 = 0; k0 < DM; k0 += 32) {
#pragma unroll
        for (int u = 0; u < 4; u++) {
            const int r = srow + 32 * u;
            float4 v = *(const float4*)&A[(size_t)(m0 + r) * DM + k0 + scol];
            uint32_t h0, l0, h1, l1;
            split2(v.x, v.y, h0, l0);
            split2(v.z, v.w, h1, l1);
            AsH[r * 20 + (scol >> 1)] = h0; AsH[r * 20 + (scol >> 1) + 1] = h1;
            AsL[r * 20 + (scol >> 1)] = l0; AsL[r * 20 + (scol >> 1) + 1] = l1;
        }
#pragma unroll
        for (int u = 0; u < 2; u++) {
            const int r = srow + 32 * u;
            float4 v = *(const float4*)&W[(size_t)(n0 + r) * DM + k0 + scol];
            uint32_t h0, l0, h1, l1;
            split2(v.x, v.y, h0, l0);
            split2(v.z, v.w, h1, l1);
            WsH[r * 20 + (scol >> 1)] = h0; WsH[r * 20 + (scol >> 1) + 1] = h1;
            WsL[r * 20 + (scol >> 1)] = l0; WsL[r * 20 + (scol >> 1) + 1] = l1;
        }
        __syncthreads();

#pragma unroll
        for (int kc = 0; kc < 2; kc++) {   // k16 chunks
            uint32_t ah[2][4], al[2][4];
#pragma unroll
            for (int mt = 0; mt < 2; mt++) {
                const int r = (wm + mt * 16 + g) * 20 + kc * 8 + tg;
                ah[mt][0] = AsH[r];            ah[mt][1] = AsH[r + 8 * 20];
                ah[mt][2] = AsH[r + 4];        ah[mt][3] = AsH[r + 8 * 20 + 4];
                al[mt][0] = AsL[r];            al[mt][1] = AsL[r + 8 * 20];
                al[mt][2] = AsL[r + 4];        al[mt][3] = AsL[r + 8 * 20 + 4];
            }
#pragma unroll
            for (int nt = 0; nt < 4; nt++) {
                const int wb = (wn + nt * 8 + g) * 20 + kc * 8 + tg;
                uint32_t bh[2] = {WsH[wb], WsH[wb + 4]};
                uint32_t bl[2] = {WsL[wb], WsL[wb + 4]};
#pragma unroll
                for (int mt = 0; mt < 2; mt++) {
                    mmabf(acc[mt][nt], ah[mt], bh);
                    mmabf(acc[mt][nt], ah[mt], bl);
                    mmabf(acc[mt][nt], al[mt], bh);
                }
            }
        }
        __syncthreads();
    }

#pragma unroll
    for (int mt = 0; mt < 2; mt++)
#pragma unroll
        for (int nt = 0; nt < 4; nt++) {
            const int row = m0 + wm + mt * 16 + g;
            const int col = n0 + wn + nt * 8 + 2 * tg;
            float2 lo = {acc[mt][nt][0], acc[mt][nt][1]};
            float2 hi = {acc[mt][nt][2], acc[mt][nt][3]};
            *(float2*)&C[(size_t)row * DM + col] = lo;
            *(float2*)&C[(size_t)(row + 8) * DM + col] = hi;
        }
}

// ---------------------------------------------------------------------------
// Flash attention, bf16x3 MMA.
// Block = (b, h, 128 q-rows). 8 warps x 16 rows. KV tiles of 64.
// smem (u32, stride 36 == 4 mod 32):
//   KsH/KsL [64 kv][32 hd-pairs], VsTH/VsTL [64 hd][32 kv-pairs],
//   PsH/PsL [128 row][32 kv-pairs], Ms[64]
// ---------------------------------------------------------------------------
#define ST 36
#define OFF_KH 0
#define OFF_KL (OFF_KH + 64 * ST)
#define OFF_VH (OFF_KL + 64 * ST)
#define OFF_VL (OFF_VH + 64 * ST)
#define OFF_PH (OFF_VL + 64 * ST)
#define OFF_PL (OFF_PH + 128 * ST)
#define OFF_M  (OFF_PL + 128 * ST)
#define SM_U32 (OFF_M + 64)

extern __shared__ uint32_t fa_smem[];

__global__ __launch_bounds__(256) void flash_attn_bf3(const int* __restrict__ mask)
{
    uint32_t* KsH = fa_smem + OFF_KH;
    uint32_t* KsL = fa_smem + OFF_KL;
    uint32_t* VsTH = fa_smem + OFF_VH;
    uint32_t* VsTL = fa_smem + OFF_VL;
    uint32_t* PsH = fa_smem + OFF_PH;
    uint32_t* PsL = fa_smem + OFF_PL;
    int* Ms = (int*)(fa_smem + OFF_M);

    const int tid = threadIdx.x, lane = tid & 31, warp = tid >> 5;
    const int g = lane >> 2, tg = lane & 3;
    const int q0 = blockIdx.x * 128, h = blockIdx.y, b = blockIdx.z;
    const int wm = warp * 16;

    // Q fragments (pre-scaled by 1/8), hi/lo split, register-resident.
    uint32_t qh[4][4], ql[4][4];
    {
        const float* Qb = g_Qh + (size_t)(b * SEQ + q0 + wm) * DM + h * HD;
#pragma unroll
        for (int kc = 0; kc < 4; kc++) {
            const int c0 = kc * 16 + 2 * tg;
#pragma unroll
            for (int half = 0; half < 2; half++) {   // k offset 0 / +8
                float2 r0 = *(const float2*)&Qb[(size_t)g * DM + c0 + half * 8];
                float2 r1 = *(const float2*)&Qb[(size_t)(g + 8) * DM + c0 + half * 8];
                split2(0.125f * r0.x, 0.125f * r0.y, qh[kc][half * 2], ql[kc][half * 2]);
                split2(0.125f * r1.x, 0.125f * r1.y, qh[kc][half * 2 + 1], ql[kc][half * 2 + 1]);
            }
        }
    }

    float o[8][4];
#pragma unroll
    for (int nt = 0; nt < 8; nt++)
#pragma unroll
        for (int j = 0; j < 4; j++) o[nt][j] = 0.f;
    float m0r = -3.0e38f, m1r = -3.0e38f, l0 = 0.f, l1 = 0.f;

    const float* Kg = g_Kh + (size_t)b * SEQ * DM + h * HD;
    const float* Vg = g_Vh + (size_t)b * SEQ * DM + h * HD;
    const int* mp = mask + b * SEQ;

    const int lrow = tid >> 4;          // 0..15
    const int lcol = (tid & 15) * 4;    // 0..60

    for (int kv0 = 0; kv0 < SEQ; kv0 += 64) {
        __syncthreads();   // previous iteration's readers done
        // Stage K (row-major pairs) and V (transposed) hi/lo tiles
#pragma unroll
        for (int u = 0; u < 4; u++) {
            const int r = lrow + 16 * u;
            float4 k4 = *(const float4*)&Kg[(size_t)(kv0 + r) * DM + lcol];
            uint32_t h0, l0w, h1, l1w;
            split2(k4.x, k4.y, h0, l0w);
            split2(k4.z, k4.w, h1, l1w);
            KsH[r * ST + (lcol >> 1)] = h0; KsH[r * ST + (lcol >> 1) + 1] = h1;
            KsL[r * ST + (lcol >> 1)] = l0w; KsL[r * ST + (lcol >> 1) + 1] = l1w;

            float4 v4 = *(const float4*)&Vg[(size_t)(kv0 + r) * DM + lcol];
            float vv[4] = {v4.x, v4.y, v4.z, v4.w};
#pragma unroll
            for (int i = 0; i < 4; i++) {
                __nv_bfloat16 hb = __float2bfloat16_rn(vv[i]);
                __nv_bfloat16 lb = __float2bfloat16_rn(vv[i] - __bfloat162float(hb));
                ((__nv_bfloat16*)VsTH)[(lcol + i) * (2 * ST) + r] = hb;
                ((__nv_bfloat16*)VsTL)[(lcol + i) * (2 * ST) + r] = lb;
            }
        }
        if (tid < 16) *(int4*)&Ms[tid * 4] = *(const int4*)&mp[kv0 + tid * 4];
        __syncthreads();

        // S = (Q*scale) K^T : per warp 16x64 via 8 n-tiles x 4 k16 chunks x 3 terms
        float s[8][4];
#pragma unroll
        for (int nt = 0; nt < 8; nt++) {
#pragma unroll
            for (int j = 0; j < 4; j++) s[nt][j] = 0.f;
            const int kb = (nt * 8 + g) * ST + tg;
#pragma unroll
            for (int kc = 0; kc < 4; kc++) {
                uint32_t bh[2] = {KsH[kb + kc * 8], KsH[kb + kc * 8 + 4]};
                uint32_t bl[2] = {KsL[kb + kc * 8], KsL[kb + kc * 8 + 4]};
                mmabf(s[nt], qh[kc], bh);
                mmabf(s[nt], qh[kc], bl);
                mmabf(s[nt], ql[kc], bh);
            }
        }

        // Per-key mask: attn_mask == 0 -> -1e30 (matches reference exactly)
#pragma unroll
        for (int nt = 0; nt < 8; nt++) {
            int2 mv = *(const int2*)&Ms[nt * 8 + 2 * tg];
            if (mv.x == 0) { s[nt][0] = -1.0e30f; s[nt][2] = -1.0e30f; }
            if (mv.y == 0) { s[nt][1] = -1.0e30f; s[nt][3] = -1.0e30f; }
        }

        // Online softmax: row g held by lanes tg=0..3 (shfl 1,2), row g+8 ditto.
        float mx0 = -3.0e38f, mx1 = -3.0e38f;
#pragma unroll
        for (int nt = 0; nt < 8; nt++) {
            mx0 = fmaxf(mx0, fmaxf(s[nt][0], s[nt][1]));
            mx1 = fmaxf(mx1, fmaxf(s[nt][2], s[nt][3]));
        }
        mx0 = fmaxf(mx0, __shfl_xor_sync(0xffffffffu, mx0, 1));
        mx0 = fmaxf(mx0, __shfl_xor_sync(0xffffffffu, mx0, 2));
        mx1 = fmaxf(mx1, __shfl_xor_sync(0xffffffffu, mx1, 1));
        mx1 = fmaxf(mx1, __shfl_xor_sync(0xffffffffu, mx1, 2));

        const float mn0 = fmaxf(m0r, mx0), mn1 = fmaxf(m1r, mx1);
        const float al0 = __expf(m0r - mn0), al1 = __expf(m1r - mn1);
        float sm0 = 0.f, sm1 = 0.f;
#pragma unroll
        for (int nt = 0; nt < 8; nt++) {
            float p0 = __expf(s[nt][0] - mn0);
            float p1 = __expf(s[nt][1] - mn0);
            float p2 = __expf(s[nt][2] - mn1);
            float p3 = __expf(s[nt][3] - mn1);
            sm0 += p0 + p1;
            sm1 += p2 + p3;
            uint32_t hp, lp;
            split2(p0, p1, hp, lp);
            PsH[(wm + g) * ST + nt * 4 + tg] = hp;
            PsL[(wm + g) * ST + nt * 4 + tg] = lp;
            split2(p2, p3, hp, lp);
            PsH[(wm + g + 8) * ST + nt * 4 + tg] = hp;
            PsL[(wm + g + 8) * ST + nt * 4 + tg] = lp;
        }
        sm0 += __shfl_xor_sync(0xffffffffu, sm0, 1);
        sm0 += __shfl_xor_sync(0xffffffffu, sm0, 2);
        sm1 += __shfl_xor_sync(0xffffffffu, sm1, 1);
        sm1 += __shfl_xor_sync(0xffffffffu, sm1, 2);
        l0 = l0 * al0 + sm0;
        l1 = l1 * al1 + sm1;
        m0r = mn0; m1r = mn1;
#pragma unroll
        for (int nt = 0; nt < 8; nt++) {
            o[nt][0] *= al0; o[nt][1] *= al0;
            o[nt][2] *= al1; o[nt][3] *= al1;
        }
        __syncwarp();   // Ps rows are warp-private; cross-lane visibility

        // O += P V : 4 k16 chunks (kv) x 8 n-tiles (hd) x 3 terms
#pragma unroll
        for (int kc = 0; kc < 4; kc++) {
            uint32_t ph[4], pl[4];
            const int pb = (wm + g) * ST + kc * 8 + tg;
            ph[0] = PsH[pb];            ph[1] = PsH[pb + 8 * ST];
            ph[2] = PsH[pb + 4];        ph[3] = PsH[pb + 8 * ST + 4];
            pl[0] = PsL[pb];            pl[1] = PsL[pb + 8 * ST];
            pl[2] = PsL[pb + 4];        pl[3] = PsL[pb + 8 * ST + 4];
#pragma unroll
            for (int nt = 0; nt < 8; nt++) {
                const int vb = (nt * 8 + g) * ST + kc * 8 + tg;
                uint32_t vh[2] = {VsTH[vb], VsTH[vb + 4]};
                uint32_t vl[2] = {VsTL[vb], VsTL[vb + 4]};
                mmabf(o[nt], ph, vh);
                mmabf(o[nt], ph, vl);
                mmabf(o[nt], pl, vh);
            }
        }
    }

    // Epilogue: normalize and store attn_vec slice
    const float i0 = 1.f / l0, i1 = 1.f / l1;
    float* Ob = g_Av + (size_t)(b * SEQ + q0 + wm) * DM + h * HD;
#pragma unroll
    for (int nt = 0; nt < 8; nt++) {
        const int col = nt * 8 + 2 * tg;
        float2 lo = {o[nt][0] * i0, o[nt][1] * i0};
        float2 hi = {o[nt][2] * i1, o[nt][3] * i1};
        *(float2*)&Ob[(size_t)g * DM + col] = lo;
        *(float2*)&Ob[(size_t)(g + 8) * DM + col] = hi;
    }
}

// ---------------------------------------------------------------------------
// Launch
// ---------------------------------------------------------------------------
extern "C" void kernel_launch(void* const* d_in, const int* in_sizes, int n_in,
                              void* d_out, int out_size)
{
    const float* query = (const float*)d_in[0];
    const float* key_  = (const float*)d_in[1];
    const float* value = (const float*)d_in[2];
    const float* Wq    = (const float*)d_in[3];
    const float* Wk    = (const float*)d_in[4];
    const float* Wv    = (const float*)d_in[5];
    const float* Wo    = (const float*)d_in[6];
    const int*   mask  = (const int*)d_in[7];
    float* out = (float*)d_out;

    float *Qh, *Kh, *Vh, *Av;
    cudaGetSymbolAddress((void**)&Qh, g_Qh);
    cudaGetSymbolAddress((void**)&Kh, g_Kh);
    cudaGetSymbolAddress((void**)&Vh, g_Vh);
    cudaGetSymbolAddress((void**)&Av, g_Av);

    const int M = B_ * SEQ;  // 8192

    dim3 gGrid(DM / 64, M / 128);   // (8, 64)
    dim3 gBlk(256);

    // Projections (bf16x3 tensor-core, ~fp32 accuracy)
    gemm_bf3<<<gGrid, gBlk>>>(query, Wq, Qh, M);
    gemm_bf3<<<gGrid, gBlk>>>(key_,  Wk, Kh, M);
    gemm_bf3<<<gGrid, gBlk>>>(value, Wv, Vh, M);

    // Attention (flash, bf16x3 tensor-core, fused mask + online softmax)
    cudaFuncSetAttribute(flash_attn_bf3,
                         cudaFuncAttributeMaxDynamicSharedMemorySize,
                         SM_U32 * 4);
    dim3 fGrid(SEQ / 128, NH, B_);  // (16, 8, 4)
    flash_attn_bf3<<<fGrid, 256, SM_U32 * 4>>>(mask);

    // Output projection
    gemm_bf3<<<gGrid, gBlk>>>(Av, Wo, out, M);
}

// round 5
// speedup vs baseline: 2.3837x; 1.3939x over previous
#include <cuda_runtime.h>
#include <cuda_bf16.h>
#include <cstdint>

// Problem constants
#define B_   4
#define SEQ  2048
#define DM   512
#define NH   8
#define HD   64

// Scratch (device globals — no allocation allowed in kernel_launch)
__device__ float g_Qh[B_ * SEQ * DM];
__device__ float g_Kh[B_ * SEQ * DM];
__device__ float g_Vh[B_ * SEQ * DM];
__device__ float g_Av[B_ * SEQ * DM];

// ---------------------------------------------------------------------------
// bf16 split helpers: x = hi + lo, hi = bf16(x), lo = bf16(x - hi).
// Packed bf16x2: element k in LOWER half, k+1 in UPPER half.
// ---------------------------------------------------------------------------
__device__ __forceinline__ void split2(float x0, float x1,
                                       uint32_t& hp, uint32_t& lp) {
    float h0 = __bfloat162float(__float2bfloat16_rn(x0));
    float h1 = __bfloat162float(__float2bfloat16_rn(x1));
    asm("cvt.rn.bf16x2.f32 %0, %1, %2;" : "=r"(hp) : "f"(h1), "f"(h0));
    asm("cvt.rn.bf16x2.f32 %0, %1, %2;" : "=r"(lp) : "f"(x1 - h1), "f"(x0 - h0));
}

// D += A(16x16) * B(16x8), bf16 in, fp32 accum. (g = lane>>2, tg = lane&3)
__device__ __forceinline__ void mmabf(float* d, const uint32_t* a, const uint32_t* b) {
    asm volatile(
        "mma.sync.aligned.m16n8k16.row.col.f32.bf16.bf16.f32 "
        "{%0,%1,%2,%3}, {%4,%5,%6,%7}, {%8,%9}, {%0,%1,%2,%3};"
        : "+f"(d[0]), "+f"(d[1]), "+f"(d[2]), "+f"(d[3])
        : "r"(a[0]), "r"(a[1]), "r"(a[2]), "r"(a[3]), "r"(b[0]), "r"(b[1]));
}

__device__ __forceinline__ void ldsm4(uint32_t* r, uint32_t addr) {
    asm volatile("ldmatrix.sync.aligned.m8n8.x4.shared.b16 {%0,%1,%2,%3}, [%4];"
                 : "=r"(r[0]), "=r"(r[1]), "=r"(r[2]), "=r"(r[3]) : "r"(addr));
}
__device__ __forceinline__ void ldsm4t(uint32_t* r, uint32_t addr) {
    asm volatile("ldmatrix.sync.aligned.m8n8.x4.trans.shared.b16 {%0,%1,%2,%3}, [%4];"
                 : "=r"(r[0]), "=r"(r[1]), "=r"(r[2]), "=r"(r[3]) : "r"(addr));
}

// ---------------------------------------------------------------------------
// Projection GEMM (NT, bf16x3): C[M,512] = A[M,512] * W[512,512]^T
// Block 128x64, BK=32, 8 warps 4(m)x2(n), warp tile 32x32. ldmatrix frags.
// smem stride 20 u32 (rows step 20 == 4 mod 32 -> LDSM conflict-free).
// ---------------------------------------------------------------------------
__global__ __launch_bounds__(256) void gemm_bf3(
    const float* __restrict__ A, const float* __restrict__ W,
    float* __restrict__ C, int M)
{
    __shared__ uint32_t AsH[128 * 20], AsL[128 * 20];
    __shared__ uint32_t WsH[64 * 20],  WsL[64 * 20];

    const int tid = threadIdx.x, lane = tid & 31, warp = tid >> 5;
    const int g = lane >> 2, tg = lane & 3;
    const int mat = lane >> 3, l7 = lane & 7;
    const int m0 = blockIdx.y * 128, n0 = blockIdx.x * 64;
    const int wm = (warp >> 1) * 32, wn = (warp & 1) * 32;

    // Per-lane ldmatrix byte addresses
    const int rowA = (mat & 1) * 8 + l7, colA = (mat >> 1) * 4;   // A-frag
    const int rowW = (mat >> 1) * 8 + l7, colW = (mat & 1) * 4;   // B-frag
    const uint32_t bAH = (uint32_t)__cvta_generic_to_shared(AsH) + 4 * ((wm + rowA) * 20 + colA);
    const uint32_t bAL = (uint32_t)__cvta_generic_to_shared(AsL) + 4 * ((wm + rowA) * 20 + colA);
    const uint32_t bWH = (uint32_t)__cvta_generic_to_shared(WsH) + 4 * ((wn + rowW) * 20 + colW);
    const uint32_t bWL = (uint32_t)__cvta_generic_to_shared(WsL) + 4 * ((wn + rowW) * 20 + colW);

    float acc[2][4][4];
#pragma unroll
    for (int mt = 0; mt < 2; mt++)
#pragma unroll
        for (int nt = 0; nt < 4; nt++)
#pragma unroll
            for (int j = 0; j < 4; j++) acc[mt][nt][j] = 0.f;

    const int srow = tid >> 3, scol = (tid & 7) * 4;

    for (int k0 = 0; k0 < DM; k0 += 32) {
#pragma unroll
        for (int u = 0; u < 4; u++) {
            const int r = srow + 32 * u;
            float4 v = *(const float4*)&A[(size_t)(m0 + r) * DM + k0 + scol];
            uint32_t h0, l0, h1, l1;
            split2(v.x, v.y, h0, l0);
            split2(v.z, v.w, h1, l1);
            AsH[r * 20 + (scol >> 1)] = h0; AsH[r * 20 + (scol >> 1) + 1] = h1;
            AsL[r * 20 + (scol >> 1)] = l0; AsL[r * 20 + (scol >> 1) + 1] = l1;
        }
#pragma unroll
        for (int u = 0; u < 2; u++) {
            const int r = srow + 32 * u;
            float4 v = *(const float4*)&W[(size_t)(n0 + r) * DM + k0 + scol];
            uint32_t h0, l0, h1, l1;
            split2(v.x, v.y, h0, l0);
            split2(v.z, v.w, h1, l1);
            WsH[r * 20 + (scol >> 1)] = h0; WsH[r * 20 + (scol >> 1) + 1] = h1;
            WsL[r * 20 + (scol >> 1)] = l0; WsL[r * 20 + (scol >> 1) + 1] = l1;
        }
        __syncthreads();

#pragma unroll
        for (int kc = 0; kc < 2; kc++) {
            uint32_t ah[2][4], al[2][4];
            ldsm4(ah[0], bAH + 4 * (kc * 8));
            ldsm4(ah[1], bAH + 4 * (16 * 20 + kc * 8));
            ldsm4(al[0], bAL + 4 * (kc * 8));
            ldsm4(al[1], bAL + 4 * (16 * 20 + kc * 8));
#pragma unroll
            for (int ntp = 0; ntp < 2; ntp++) {
                uint32_t bh[4], bl[4];
                ldsm4(bh, bWH + 4 * (ntp * 16 * 20 + kc * 8));
                ldsm4(bl, bWL + 4 * (ntp * 16 * 20 + kc * 8));
#pragma unroll
                for (int mt = 0; mt < 2; mt++) {
                    mmabf(acc[mt][2 * ntp],     ah[mt], bh);
                    mmabf(acc[mt][2 * ntp],     ah[mt], bl);
                    mmabf(acc[mt][2 * ntp],     al[mt], bh);
                    mmabf(acc[mt][2 * ntp + 1], ah[mt], bh + 2);
                    mmabf(acc[mt][2 * ntp + 1], ah[mt], bl + 2);
                    mmabf(acc[mt][2 * ntp + 1], al[mt], bh + 2);
                }
            }
        }
        __syncthreads();
    }

#pragma unroll
    for (int mt = 0; mt < 2; mt++)
#pragma unroll
        for (int nt = 0; nt < 4; nt++) {
            const int row = m0 + wm + mt * 16 + g;
            const int col = n0 + wn + nt * 8 + 2 * tg;
            float2 lo = {acc[mt][nt][0], acc[mt][nt][1]};
            float2 hi = {acc[mt][nt][2], acc[mt][nt][3]};
            *(float2*)&C[(size_t)row * DM + col] = lo;
            *(float2*)&C[(size_t)(row + 8) * DM + col] = hi;
        }
}

// ---------------------------------------------------------------------------
// Flash attention, bf16x3 MMA, FA2-style register P, ldmatrix fragments.
// Block = (b, h, 128 q-rows). 8 warps x 16 rows. KV tiles of 64.
// smem (u32, stride 36): KsH/KsL [64 kv][32 hd-pairs], VsH/VsL [64 kv][32 hd-pairs]
// (V natural; transposed at load via ldmatrix.trans), Ms[64].
// ---------------------------------------------------------------------------
#define ST 36
#define OFF_KH 0
#define OFF_KL (OFF_KH + 64 * ST)
#define OFF_VH (OFF_KL + 64 * ST)
#define OFF_VL (OFF_VH + 64 * ST)
#define OFF_M  (OFF_VL + 64 * ST)
#define SM_U32 (OFF_M + 64)

extern __shared__ uint32_t fa_smem[];

__global__ __launch_bounds__(256, 2) void flash_attn_bf3(const int* __restrict__ mask)
{
    uint32_t* KsH = fa_smem + OFF_KH;
    uint32_t* KsL = fa_smem + OFF_KL;
    uint32_t* VsH = fa_smem + OFF_VH;
    uint32_t* VsL = fa_smem + OFF_VL;
    int* Ms = (int*)(fa_smem + OFF_M);

    const int tid = threadIdx.x, lane = tid & 31, warp = tid >> 5;
    const int g = lane >> 2, tg = lane & 3;
    const int mat = lane >> 3, l7 = lane & 7;
    const int q0 = blockIdx.x * 128, h = blockIdx.y, b = blockIdx.z;
    const int wm = warp * 16;

    const uint32_t sbase = (uint32_t)__cvta_generic_to_shared(fa_smem);
    // K b-frag lanes: row = kv (per n-tile), col = hd k-halves
    const uint32_t aKH = sbase + 4 * (OFF_KH + ((mat >> 1) * 8 + l7) * ST + (mat & 1) * 4);
    const uint32_t aKL = sbase + 4 * (OFF_KL + ((mat >> 1) * 8 + l7) * ST + (mat & 1) * 4);
    // V trans b-frag lanes: row = kv k-halves, col = hd n-tile halves
    const uint32_t aVH = sbase + 4 * (OFF_VH + ((mat & 1) * 8 + l7) * ST + (mat >> 1) * 4);
    const uint32_t aVL = sbase + 4 * (OFF_VL + ((mat & 1) * 8 + l7) * ST + (mat >> 1) * 4);

    // Q fragments (pre-scaled by 1/8), hi/lo split, register-resident.
    uint32_t qh[4][4], ql[4][4];
    {
        const float* Qb = g_Qh + (size_t)(b * SEQ + q0 + wm) * DM + h * HD;
#pragma unroll
        for (int kc = 0; kc < 4; kc++) {
            const int c0 = kc * 16 + 2 * tg;
#pragma unroll
            for (int half = 0; half < 2; half++) {
                float2 r0 = *(const float2*)&Qb[(size_t)g * DM + c0 + half * 8];
                float2 r1 = *(const float2*)&Qb[(size_t)(g + 8) * DM + c0 + half * 8];
                split2(0.125f * r0.x, 0.125f * r0.y, qh[kc][half * 2], ql[kc][half * 2]);
                split2(0.125f * r1.x, 0.125f * r1.y, qh[kc][half * 2 + 1], ql[kc][half * 2 + 1]);
            }
        }
    }

    float o[8][4];
#pragma unroll
    for (int nt = 0; nt < 8; nt++)
#pragma unroll
        for (int j = 0; j < 4; j++) o[nt][j] = 0.f;
    float m0r = -3.0e38f, m1r = -3.0e38f, l0 = 0.f, l1 = 0.f;

    const float* Kg = g_Kh + (size_t)b * SEQ * DM + h * HD;
    const float* Vg = g_Vh + (size_t)b * SEQ * DM + h * HD;
    const int* mp = mask + b * SEQ;

    const int lrow = tid >> 4, lcol = (tid & 15) * 4;

    for (int kv0 = 0; kv0 < SEQ; kv0 += 64) {
        __syncthreads();
        // Stage K and V tiles (both natural layout, hi/lo pair-packed)
#pragma unroll
        for (int u = 0; u < 4; u++) {
            const int r = lrow + 16 * u;
            float4 k4 = *(const float4*)&Kg[(size_t)(kv0 + r) * DM + lcol];
            uint32_t h0, l0w, h1, l1w;
            split2(k4.x, k4.y, h0, l0w);
            split2(k4.z, k4.w, h1, l1w);
            KsH[r * ST + (lcol >> 1)] = h0; KsH[r * ST + (lcol >> 1) + 1] = h1;
            KsL[r * ST + (lcol >> 1)] = l0w; KsL[r * ST + (lcol >> 1) + 1] = l1w;
            float4 v4 = *(const float4*)&Vg[(size_t)(kv0 + r) * DM + lcol];
            split2(v4.x, v4.y, h0, l0w);
            split2(v4.z, v4.w, h1, l1w);
            VsH[r * ST + (lcol >> 1)] = h0; VsH[r * ST + (lcol >> 1) + 1] = h1;
            VsL[r * ST + (lcol >> 1)] = l0w; VsL[r * ST + (lcol >> 1) + 1] = l1w;
        }
        if (tid < 16) *(int4*)&Ms[tid * 4] = *(const int4*)&mp[kv0 + tid * 4];
        __syncthreads();

        // S = (Q*scale) K^T : 4 nt-pairs x 4 k16 chunks, ldmatrix B-frags
        float s[8][4];
#pragma unroll
        for (int nt = 0; nt < 8; nt++)
#pragma unroll
            for (int j = 0; j < 4; j++) s[nt][j] = 0.f;
#pragma unroll
        for (int ntp = 0; ntp < 4; ntp++) {
#pragma unroll
            for (int kc = 0; kc < 4; kc++) {
                uint32_t bh[4], bl[4];
                ldsm4(bh, aKH + 4 * (ntp * 16 * ST + kc * 8));
                ldsm4(bl, aKL + 4 * (ntp * 16 * ST + kc * 8));
                mmabf(s[2 * ntp],     qh[kc], bh);
                mmabf(s[2 * ntp],     qh[kc], bl);
                mmabf(s[2 * ntp],     ql[kc], bh);
                mmabf(s[2 * ntp + 1], qh[kc], bh + 2);
                mmabf(s[2 * ntp + 1], qh[kc], bl + 2);
                mmabf(s[2 * ntp + 1], ql[kc], bh + 2);
            }
        }

        // Per-key mask: attn_mask == 0 -> -1e30
#pragma unroll
        for (int nt = 0; nt < 8; nt++) {
            int2 mv = *(const int2*)&Ms[nt * 8 + 2 * tg];
            if (mv.x == 0) { s[nt][0] = -1.0e30f; s[nt][2] = -1.0e30f; }
            if (mv.y == 0) { s[nt][1] = -1.0e30f; s[nt][3] = -1.0e30f; }
        }

        // Online softmax (rows g and g+8, lanes tg 0..3 share a row)
        float mx0 = -3.0e38f, mx1 = -3.0e38f;
#pragma unroll
        for (int nt = 0; nt < 8; nt++) {
            mx0 = fmaxf(mx0, fmaxf(s[nt][0], s[nt][1]));
            mx1 = fmaxf(mx1, fmaxf(s[nt][2], s[nt][3]));
        }
        mx0 = fmaxf(mx0, __shfl_xor_sync(0xffffffffu, mx0, 1));
        mx0 = fmaxf(mx0, __shfl_xor_sync(0xffffffffu, mx0, 2));
        mx1 = fmaxf(mx1, __shfl_xor_sync(0xffffffffu, mx1, 1));
        mx1 = fmaxf(mx1, __shfl_xor_sync(0xffffffffu, mx1, 2));

        const float mn0 = fmaxf(m0r, mx0), mn1 = fmaxf(m1r, mx1);
        const float al0 = __expf(m0r - mn0), al1 = __expf(m1r - mn1);
        float sm0 = 0.f, sm1 = 0.f;
#pragma unroll
        for (int nt = 0; nt < 8; nt++) {
            s[nt][0] = __expf(s[nt][0] - mn0);
            s[nt][1] = __expf(s[nt][1] - mn0);
            s[nt][2] = __expf(s[nt][2] - mn1);
            s[nt][3] = __expf(s[nt][3] - mn1);
            sm0 += s[nt][0] + s[nt][1];
            sm1 += s[nt][2] + s[nt][3];
        }
        sm0 += __shfl_xor_sync(0xffffffffu, sm0, 1);
        sm0 += __shfl_xor_sync(0xffffffffu, sm0, 2);
        sm1 += __shfl_xor_sync(0xffffffffu, sm1, 1);
        sm1 += __shfl_xor_sync(0xffffffffu, sm1, 2);
        l0 = l0 * al0 + sm0;
        l1 = l1 * al1 + sm1;
        m0r = mn0; m1r = mn1;
#pragma unroll
        for (int nt = 0; nt < 8; nt++) {
            o[nt][0] *= al0; o[nt][1] *= al0;
            o[nt][2] *= al1; o[nt][3] *= al1;
        }

        // Pack P into A-fragments (register-only, no smem round trip):
        // a0=(g, kv 2tg pair) -> s[2kc][0..1], a1=(g+8) -> s[2kc][2..3],
        // a2=(g, +8) -> s[2kc+1][0..1], a3=(g+8, +8) -> s[2kc+1][2..3]
        uint32_t pah[4][4], pal[4][4];
#pragma unroll
        for (int kc = 0; kc < 4; kc++) {
            split2(s[2 * kc][0],     s[2 * kc][1],     pah[kc][0], pal[kc][0]);
            split2(s[2 * kc][2],     s[2 * kc][3],     pah[kc][1], pal[kc][1]);
            split2(s[2 * kc + 1][0], s[2 * kc + 1][1], pah[kc][2], pal[kc][2]);
            split2(s[2 * kc + 1][2], s[2 * kc + 1][3], pah[kc][3], pal[kc][3]);
        }

        // O += P V : ldmatrix.trans B-frags from natural V
#pragma unroll
        for (int ntp = 0; ntp < 4; ntp++) {
#pragma unroll
            for (int kc = 0; kc < 4; kc++) {
                uint32_t vh[4], vl[4];
                ldsm4t(vh, aVH + 4 * (kc * 16 * ST + ntp * 8));
                ldsm4t(vl, aVL + 4 * (kc * 16 * ST + ntp * 8));
                mmabf(o[2 * ntp],     pah[kc], vh);
                mmabf(o[2 * ntp],     pah[kc], vl);
                mmabf(o[2 * ntp],     pal[kc], vh);
                mmabf(o[2 * ntp + 1], pah[kc], vh + 2);
                mmabf(o[2 * ntp + 1], pah[kc], vl + 2);
                mmabf(o[2 * ntp + 1], pal[kc], vh + 2);
            }
        }
    }

    // Epilogue: normalize and store attn_vec slice
    const float i0 = 1.f / l0, i1 = 1.f / l1;
    float* Ob = g_Av + (size_t)(b * SEQ + q0 + wm) * DM + h * HD;
#pragma unroll
    for (int nt = 0; nt < 8; nt++) {
        const int col = nt * 8 + 2 * tg;
        float2 lo = {o[nt][0] * i0, o[nt][1] * i0};
        float2 hi = {o[nt][2] * i1, o[nt][3] * i1};
        *(float2*)&Ob[(size_t)g * DM + col] = lo;
        *(float2*)&Ob[(size_t)(g + 8) * DM + col] = hi;
    }
}

// ---------------------------------------------------------------------------
// Launch
// ---------------------------------------------------------------------------
extern "C" void kernel_launch(void* const* d_in, const int* in_sizes, int n_in,
                              void* d_out, int out_size)
{
    const float* query = (const float*)d_in[0];
    const float* key_  = (const float*)d_in[1];
    const float* value = (const float*)d_in[2];
    const float* Wq    = (const float*)d_in[3];
    const float* Wk    = (const float*)d_in[4];
    const float* Wv    = (const float*)d_in[5];
    const float* Wo    = (const float*)d_in[6];
    const int*   mask  = (const int*)d_in[7];
    float* out = (float*)d_out;

    float *Qh, *Kh, *Vh, *Av;
    cudaGetSymbolAddress((void**)&Qh, g_Qh);
    cudaGetSymbolAddress((void**)&Kh, g_Kh);
    cudaGetSymbolAddress((void**)&Vh, g_Vh);
    cudaGetSymbolAddress((void**)&Av, g_Av);

    const int M = B_ * SEQ;  // 8192

    dim3 gGrid(DM / 64, M / 128);   // (8, 64)
    dim3 gBlk(256);

    // Projections (bf16x3 tensor-core)
    gemm_bf3<<<gGrid, gBlk>>>(query, Wq, Qh, M);
    gemm_bf3<<<gGrid, gBlk>>>(key_,  Wk, Kh, M);
    gemm_bf3<<<gGrid, gBlk>>>(value, Wv, Vh, M);

    // Attention (flash, bf16x3, register-P, ldmatrix frags)
    cudaFuncSetAttribute(flash_attn_bf3,
                         cudaFuncAttributeMaxDynamicSharedMemorySize,
                         SM_U32 * 4);
    dim3 fGrid(SEQ / 128, NH, B_);  // (16, 8, 4)
    flash_attn_bf3<<<fGrid, 256, SM_U32 * 4>>>(mask);

    // Output projection
    gemm_bf3<<<gGrid, gBlk>>>(Av, Wo, out, M);
}

// round 6
// speedup vs baseline: 2.4175x; 1.0142x over previous
#include <cuda_runtime.h>
#include <cuda_bf16.h>
#include <cstdint>

// Problem constants
#define B_   4
#define SEQ  2048
#define DM   512
#define NH   8
#define HD   64
#define MROWS (B_ * SEQ)     // 8192
#define ROWU  (DM / 2)       // 256 u32 (bf16 pairs) per row

// ---------------------------------------------------------------------------
// Persistent bf16 hi/lo planes (u32 = packed bf16x2 pair (2i, 2i+1))
// ---------------------------------------------------------------------------
__device__ uint32_t g_qH[MROWS * ROWU], g_qL[MROWS * ROWU];   // split(query)
__device__ uint32_t g_kH[MROWS * ROWU], g_kL[MROWS * ROWU];   // split(key)
__device__ uint32_t g_vH[MROWS * ROWU], g_vL[MROWS * ROWU];   // split(value)
__device__ uint32_t g_wqH[DM * ROWU], g_wqL[DM * ROWU];
__device__ uint32_t g_wkH[DM * ROWU], g_wkL[DM * ROWU];
__device__ uint32_t g_wvH[DM * ROWU], g_wvL[DM * ROWU];
__device__ uint32_t g_woH[DM * ROWU], g_woL[DM * ROWU];
__device__ uint32_t g_QH[MROWS * ROWU], g_QL[MROWS * ROWU];   // Q proj (split)
__device__ uint32_t g_KH[MROWS * ROWU], g_KL[MROWS * ROWU];   // K proj
__device__ uint32_t g_VH[MROWS * ROWU], g_VL[MROWS * ROWU];   // V proj
__device__ uint32_t g_AH[MROWS * ROWU], g_AL[MROWS * ROWU];   // attn out

// ---------------------------------------------------------------------------
// Helpers
// ---------------------------------------------------------------------------
__device__ __forceinline__ void split2(float x0, float x1,
                                       uint32_t& hp, uint32_t& lp) {
    float h0 = __bfloat162float(__float2bfloat16_rn(x0));
    float h1 = __bfloat162float(__float2bfloat16_rn(x1));
    asm("cvt.rn.bf16x2.f32 %0, %1, %2;" : "=r"(hp) : "f"(h1), "f"(h0));
    asm("cvt.rn.bf16x2.f32 %0, %1, %2;" : "=r"(lp) : "f"(x1 - h1), "f"(x0 - h0));
}

__device__ __forceinline__ float ex2(float x) {
    float y;
    asm("ex2.approx.ftz.f32 %0, %1;" : "=f"(y) : "f"(x));
    return y;
}

__device__ __forceinline__ void mmabf(float* d, const uint32_t* a, const uint32_t* b) {
    asm volatile(
        "mma.sync.aligned.m16n8k16.row.col.f32.bf16.bf16.f32 "
        "{%0,%1,%2,%3}, {%4,%5,%6,%7}, {%8,%9}, {%0,%1,%2,%3};"
        : "+f"(d[0]), "+f"(d[1]), "+f"(d[2]), "+f"(d[3])
        : "r"(a[0]), "r"(a[1]), "r"(a[2]), "r"(a[3]), "r"(b[0]), "r"(b[1]));
}

__device__ __forceinline__ void ldsm4(uint32_t* r, uint32_t addr) {
    asm volatile("ldmatrix.sync.aligned.m8n8.x4.shared.b16 {%0,%1,%2,%3}, [%4];"
                 : "=r"(r[0]), "=r"(r[1]), "=r"(r[2]), "=r"(r[3]) : "r"(addr));
}
__device__ __forceinline__ void ldsm4t(uint32_t* r, uint32_t addr) {
    asm volatile("ldmatrix.sync.aligned.m8n8.x4.trans.shared.b16 {%0,%1,%2,%3}, [%4];"
                 : "=r"(r[0]), "=r"(r[1]), "=r"(r[2]), "=r"(r[3]) : "r"(addr));
}
__device__ __forceinline__ void cpasync16(uint32_t dst_smem, const void* src) {
    asm volatile("cp.async.cg.shared.global [%0], [%1], 16;"
                 :: "r"(dst_smem), "l"(src));
}

// ---------------------------------------------------------------------------
// Convert: f32 -> hi/lo bf16 planes (streaming, once per tensor)
// ---------------------------------------------------------------------------
__global__ __launch_bounds__(256) void convert_split(
    const float* __restrict__ src, uint32_t* __restrict__ dh,
    uint32_t* __restrict__ dl, int n4)
{
    int i = blockIdx.x * 256 + threadIdx.x;
    if (i >= n4) return;
    float4 v = ((const float4*)src)[i];
    uint32_t h0, l0, h1, l1;
    split2(v.x, v.y, h0, l0);
    split2(v.z, v.w, h1, l1);
    ((uint2*)dh)[i] = make_uint2(h0, h1);
    ((uint2*)dl)[i] = make_uint2(l0, l1);
}

// ---------------------------------------------------------------------------
// Projection GEMM (NT, bf16x3, pre-split operands): C = A[M,512] * W[512,512]^T
// Block 128x64, BK=32, 8 warps 4(m)x2(n), warp 32x32. Register-prefetch pipeline.
// SPLIT_OUT: write hi/lo planes instead of f32.
// ---------------------------------------------------------------------------
template <bool SPLIT_OUT>
__global__ __launch_bounds__(256) void gemm_pre(
    const uint32_t* __restrict__ AH, const uint32_t* __restrict__ AL,
    const uint32_t* __restrict__ WH, const uint32_t* __restrict__ WL,
    float* __restrict__ C, uint32_t* __restrict__ CH, uint32_t* __restrict__ CL)
{
    __shared__ uint32_t AsH[128 * 20], AsL[128 * 20];
    __shared__ uint32_t WsH[64 * 20],  WsL[64 * 20];

    const int tid = threadIdx.x, lane = tid & 31, warp = tid >> 5;
    const int g = lane >> 2, tg = lane & 3;
    const int mat = lane >> 3, l7 = lane & 7;
    const int m0 = blockIdx.y * 128, n0 = blockIdx.x * 64;
    const int wm = (warp >> 1) * 32, wn = (warp & 1) * 32;

    const int rowA = (mat & 1) * 8 + l7, colA = (mat >> 1) * 4;
    const int rowW = (mat >> 1) * 8 + l7, colW = (mat & 1) * 4;
    const uint32_t bAH = (uint32_t)__cvta_generic_to_shared(AsH) + 4 * ((wm + rowA) * 20 + colA);
    const uint32_t bAL = (uint32_t)__cvta_generic_to_shared(AsL) + 4 * ((wm + rowA) * 20 + colA);
    const uint32_t bWH = (uint32_t)__cvta_generic_to_shared(WsH) + 4 * ((wn + rowW) * 20 + colW);
    const uint32_t bWL = (uint32_t)__cvta_generic_to_shared(WsL) + 4 * ((wn + rowW) * 20 + colW);

    float acc[2][4][4];
#pragma unroll
    for (int mt = 0; mt < 2; mt++)
#pragma unroll
        for (int nt = 0; nt < 4; nt++)
#pragma unroll
            for (int j = 0; j < 4; j++) acc[mt][nt][j] = 0.f;

    // Staging map: r = tid>>2 (0..63), q = (tid&3)*4 u32 cols
    const int r = tid >> 2, q = (tid & 3) * 4;

    uint4 pA0h, pA1h, pA0l, pA1l, pWh, pWl;
    {
        const int kc2 = 0;
        pA0h = *(const uint4*)&AH[(size_t)(m0 + r) * ROWU + kc2 + q];
        pA1h = *(const uint4*)&AH[(size_t)(m0 + r + 64) * ROWU + kc2 + q];
        pA0l = *(const uint4*)&AL[(size_t)(m0 + r) * ROWU + kc2 + q];
        pA1l = *(const uint4*)&AL[(size_t)(m0 + r + 64) * ROWU + kc2 + q];
        pWh  = *(const uint4*)&WH[(size_t)(n0 + r) * ROWU + kc2 + q];
        pWl  = *(const uint4*)&WL[(size_t)(n0 + r) * ROWU + kc2 + q];
    }

    for (int k0 = 0; k0 < DM; k0 += 32) {
        __syncthreads();   // previous MMA readers done
        *(uint4*)&AsH[r * 20 + q] = pA0h;
        *(uint4*)&AsH[(r + 64) * 20 + q] = pA1h;
        *(uint4*)&AsL[r * 20 + q] = pA0l;
        *(uint4*)&AsL[(r + 64) * 20 + q] = pA1l;
        *(uint4*)&WsH[r * 20 + q] = pWh;
        *(uint4*)&WsL[r * 20 + q] = pWl;
        __syncthreads();

        if (k0 + 32 < DM) {
            const int kc2 = (k0 + 32) >> 1;
            pA0h = *(const uint4*)&AH[(size_t)(m0 + r) * ROWU + kc2 + q];
            pA1h = *(const uint4*)&AH[(size_t)(m0 + r + 64) * ROWU + kc2 + q];
            pA0l = *(const uint4*)&AL[(size_t)(m0 + r) * ROWU + kc2 + q];
            pA1l = *(const uint4*)&AL[(size_t)(m0 + r + 64) * ROWU + kc2 + q];
            pWh  = *(const uint4*)&WH[(size_t)(n0 + r) * ROWU + kc2 + q];
            pWl  = *(const uint4*)&WL[(size_t)(n0 + r) * ROWU + kc2 + q];
        }

#pragma unroll
        for (int kc = 0; kc < 2; kc++) {
            uint32_t ah[2][4], al[2][4];
            ldsm4(ah[0], bAH + 4 * (kc * 8));
            ldsm4(ah[1], bAH + 4 * (16 * 20 + kc * 8));
            ldsm4(al[0], bAL + 4 * (kc * 8));
            ldsm4(al[1], bAL + 4 * (16 * 20 + kc * 8));
#pragma unroll
            for (int ntp = 0; ntp < 2; ntp++) {
                uint32_t bh[4], bl[4];
                ldsm4(bh, bWH + 4 * (ntp * 16 * 20 + kc * 8));
                ldsm4(bl, bWL + 4 * (ntp * 16 * 20 + kc * 8));
#pragma unroll
                for (int mt = 0; mt < 2; mt++) {
                    mmabf(acc[mt][2 * ntp],     ah[mt], bh);
                    mmabf(acc[mt][2 * ntp],     ah[mt], bl);
                    mmabf(acc[mt][2 * ntp],     al[mt], bh);
                    mmabf(acc[mt][2 * ntp + 1], ah[mt], bh + 2);
                    mmabf(acc[mt][2 * ntp + 1], ah[mt], bl + 2);
                    mmabf(acc[mt][2 * ntp + 1], al[mt], bh + 2);
                }
            }
        }
    }

#pragma unroll
    for (int mt = 0; mt < 2; mt++)
#pragma unroll
        for (int nt = 0; nt < 4; nt++) {
            const int row = m0 + wm + mt * 16 + g;
            if (SPLIT_OUT) {
                const int colu = (n0 + wn) / 2 + nt * 4 + tg;
                uint32_t hp, lp;
                split2(acc[mt][nt][0], acc[mt][nt][1], hp, lp);
                CH[(size_t)row * ROWU + colu] = hp;
                CL[(size_t)row * ROWU + colu] = lp;
                split2(acc[mt][nt][2], acc[mt][nt][3], hp, lp);
                CH[(size_t)(row + 8) * ROWU + colu] = hp;
                CL[(size_t)(row + 8) * ROWU + colu] = lp;
            } else {
                const int col = n0 + wn + nt * 8 + 2 * tg;
                float2 lo = {acc[mt][nt][0], acc[mt][nt][1]};
                float2 hi = {acc[mt][nt][2], acc[mt][nt][3]};
                *(float2*)&C[(size_t)row * DM + col] = lo;
                *(float2*)&C[(size_t)(row + 8) * DM + col] = hi;
            }
        }
}

// ---------------------------------------------------------------------------
// Flash attention, bf16x3 MMA, register P, cp.async double-buffered K/V.
// Block = (b, h, 128 q-rows). 8 warps x 16 rows. KV tiles of 64.
// smem (u32): 2 x [KH|KL|VH|VL] planes (64 x stride-36) + mask[2048]
// ---------------------------------------------------------------------------
#define ST 36
#define PLANE (64 * ST)        // 2304 u32
#define BUFSZ (4 * PLANE)      // 9216 u32 per stage
#define OFF_MS (2 * BUFSZ)     // 18432
#define SM_U32 (OFF_MS + SEQ)  // + 2048 ints

extern __shared__ uint32_t fa_smem[];

__global__ __launch_bounds__(256, 2) void flash_bf3(const int* __restrict__ mask)
{
    const int tid = threadIdx.x, lane = tid & 31, warp = tid >> 5;
    const int g = lane >> 2, tg = lane & 3;
    const int mat = lane >> 3, l7 = lane & 7;
    const int q0 = blockIdx.x * 128, h = blockIdx.y, b = blockIdx.z;
    const int wm = warp * 16;
    const float cs = 0.125f * 1.44269504f;   // scale * log2(e)

    int* Ms = (int*)(fa_smem + OFF_MS);
    const uint32_t sbase = (uint32_t)__cvta_generic_to_shared(fa_smem);

    // ldmatrix lane offsets (bytes, within a stage buffer)
    const uint32_t loK = 4 * (((mat >> 1) * 8 + l7) * ST + (mat & 1) * 4);
    const uint32_t loV = 4 * (((mat & 1) * 8 + l7) * ST + (mat >> 1) * 4);

    // Mask preload (whole batch row)
#pragma unroll
    for (int i = tid; i < SEQ / 4; i += 256)
        ((int4*)Ms)[i] = ((const int4*)(mask + b * SEQ))[i];

    // Q fragments from pre-split planes (no conversion, no scaling)
    uint32_t qh[4][4], ql[4][4];
    {
        const uint32_t* QHp = g_QH + (size_t)(b * SEQ + q0 + wm) * ROWU + h * 32;
        const uint32_t* QLp = g_QL + (size_t)(b * SEQ + q0 + wm) * ROWU + h * 32;
#pragma unroll
        for (int kc = 0; kc < 4; kc++) {
            const int c = kc * 8 + tg;
            qh[kc][0] = QHp[(size_t)g * ROWU + c];
            qh[kc][1] = QHp[(size_t)(g + 8) * ROWU + c];
            qh[kc][2] = QHp[(size_t)g * ROWU + c + 4];
            qh[kc][3] = QHp[(size_t)(g + 8) * ROWU + c + 4];
            ql[kc][0] = QLp[(size_t)g * ROWU + c];
            ql[kc][1] = QLp[(size_t)(g + 8) * ROWU + c];
            ql[kc][2] = QLp[(size_t)g * ROWU + c + 4];
            ql[kc][3] = QLp[(size_t)(g + 8) * ROWU + c + 4];
        }
    }

    // cp.async staging map: plane = tid>>6, 8 threads/row, 8 rows/pass
    const int pl = tid >> 6, sIn = tid & 63;
    const int rB = sIn >> 3, qc = (sIn & 7) * 4;
    const uint32_t* sp = (pl == 0) ? g_KH : (pl == 1) ? g_KL : (pl == 2) ? g_VH : g_VL;
    sp += (size_t)(b * SEQ) * ROWU + h * 32 + qc;
    const uint32_t dbase = pl * PLANE + rB * ST + qc;

#define STAGE(kv0, buf)                                                        \
    {                                                                          \
        const uint32_t d0 = sbase + 4 * ((buf) * BUFSZ + dbase);               \
        const uint32_t* s0 = sp + (size_t)(kv0 + rB) * ROWU;                   \
        _Pragma("unroll")                                                      \
        for (int u = 0; u < 8; u++)                                            \
            cpasync16(d0 + 4 * (u * 8 * ST), s0 + (size_t)(u * 8) * ROWU);     \
        asm volatile("cp.async.commit_group;");                                \
    }

    STAGE(0, 0);

    float o[8][4];
#pragma unroll
    for (int nt = 0; nt < 8; nt++)
#pragma unroll
        for (int j = 0; j < 4; j++) o[nt][j] = 0.f;
    float m0r = -3.0e38f, m1r = -3.0e38f, l0 = 0.f, l1 = 0.f;

    for (int t = 0; t < 32; t++) {
        if (t < 31) STAGE((t + 1) * 64, (t + 1) & 1);
        if (t < 31) asm volatile("cp.async.wait_group 1;");
        else        asm volatile("cp.async.wait_group 0;");
        __syncthreads();   // tile t staged for everyone; also fences mask preload

        const uint32_t bb = sbase + (t & 1) * (4 * BUFSZ);
        const uint32_t aKH = bb + loK,               aKL = bb + 4 * PLANE + loK;
        const uint32_t aVH = bb + 8 * PLANE + loV,   aVL = bb + 12 * PLANE + loV;
        const int kv0 = t * 64;

        // S = Q K^T (unscaled)
        float s[8][4];
#pragma unroll
        for (int nt = 0; nt < 8; nt++)
#pragma unroll
            for (int j = 0; j < 4; j++) s[nt][j] = 0.f;
#pragma unroll
        for (int ntp = 0; ntp < 4; ntp++) {
#pragma unroll
            for (int kc = 0; kc < 4; kc++) {
                uint32_t bh[4], bl[4];
                ldsm4(bh, aKH + 4 * (ntp * 16 * ST + kc * 8));
                ldsm4(bl, aKL + 4 * (ntp * 16 * ST + kc * 8));
                mmabf(s[2 * ntp],     qh[kc], bh);
                mmabf(s[2 * ntp],     qh[kc], bl);
                mmabf(s[2 * ntp],     ql[kc], bh);
                mmabf(s[2 * ntp + 1], qh[kc], bh + 2);
                mmabf(s[2 * ntp + 1], qh[kc], bl + 2);
                mmabf(s[2 * ntp + 1], ql[kc], bh + 2);
            }
        }

        // Per-key mask (attn_mask == 0 -> -1e30, matching reference)
#pragma unroll
        for (int nt = 0; nt < 8; nt++) {
            int2 mv = *(const int2*)&Ms[kv0 + nt * 8 + 2 * tg];
            if (mv.x == 0) { s[nt][0] = -1.0e30f; s[nt][2] = -1.0e30f; }
            if (mv.y == 0) { s[nt][1] = -1.0e30f; s[nt][3] = -1.0e30f; }
        }

        // Online softmax in log2 domain: p = exp2((s - m) * cs)
        float mx0 = -3.0e38f, mx1 = -3.0e38f;
#pragma unroll
        for (int nt = 0; nt < 8; nt++) {
            mx0 = fmaxf(mx0, fmaxf(s[nt][0], s[nt][1]));
            mx1 = fmaxf(mx1, fmaxf(s[nt][2], s[nt][3]));
        }
        mx0 = fmaxf(mx0, __shfl_xor_sync(0xffffffffu, mx0, 1));
        mx0 = fmaxf(mx0, __shfl_xor_sync(0xffffffffu, mx0, 2));
        mx1 = fmaxf(mx1, __shfl_xor_sync(0xffffffffu, mx1, 1));
        mx1 = fmaxf(mx1, __shfl_xor_sync(0xffffffffu, mx1, 2));

        const float mn0 = fmaxf(m0r, mx0), mn1 = fmaxf(m1r, mx1);
        const float al0 = ex2((m0r - mn0) * cs), al1 = ex2((m1r - mn1) * cs);
        float sm0 = 0.f, sm1 = 0.f;
#pragma unroll
        for (int nt = 0; nt < 8; nt++) {
            s[nt][0] = ex2((s[nt][0] - mn0) * cs);
            s[nt][1] = ex2((s[nt][1] - mn0) * cs);
            s[nt][2] = ex2((s[nt][2] - mn1) * cs);
            s[nt][3] = ex2((s[nt][3] - mn1) * cs);
            sm0 += s[nt][0] + s[nt][1];
            sm1 += s[nt][2] + s[nt][3];
        }
        sm0 += __shfl_xor_sync(0xffffffffu, sm0, 1);
        sm0 += __shfl_xor_sync(0xffffffffu, sm0, 2);
        sm1 += __shfl_xor_sync(0xffffffffu, sm1, 1);
        sm1 += __shfl_xor_sync(0xffffffffu, sm1, 2);
        l0 = l0 * al0 + sm0;
        l1 = l1 * al1 + sm1;
        m0r = mn0; m1r = mn1;
#pragma unroll
        for (int nt = 0; nt < 8; nt++) {
            o[nt][0] *= al0; o[nt][1] *= al0;
            o[nt][2] *= al1; o[nt][3] *= al1;
        }

        // Pack P into hi/lo A-fragments (register-only)
        uint32_t pah[4][4], pal[4][4];
#pragma unroll
        for (int kc = 0; kc < 4; kc++) {
            split2(s[2 * kc][0],     s[2 * kc][1],     pah[kc][0], pal[kc][0]);
            split2(s[2 * kc][2],     s[2 * kc][3],     pah[kc][1], pal[kc][1]);
            split2(s[2 * kc + 1][0], s[2 * kc + 1][1], pah[kc][2], pal[kc][2]);
            split2(s[2 * kc + 1][2], s[2 * kc + 1][3], pah[kc][3], pal[kc][3]);
        }

        // O += P V (ldmatrix.trans from natural V)
#pragma unroll
        for (int ntp = 0; ntp < 4; ntp++) {
#pragma unroll
            for (int kc = 0; kc < 4; kc++) {
                uint32_t vh[4], vl[4];
                ldsm4t(vh, aVH + 4 * (kc * 16 * ST + ntp * 8));
                ldsm4t(vl, aVL + 4 * (kc * 16 * ST + ntp * 8));
                mmabf(o[2 * ntp],     pah[kc], vh);
                mmabf(o[2 * ntp],     pah[kc], vl);
                mmabf(o[2 * ntp],     pal[kc], vh);
                mmabf(o[2 * ntp + 1], pah[kc], vh + 2);
                mmabf(o[2 * ntp + 1], pah[kc], vl + 2);
                mmabf(o[2 * ntp + 1], pal[kc], vh + 2);
            }
        }
        __syncthreads();   // all reads of buffer t done before restaging it
    }

    // Epilogue: normalize and store split Av planes
    const float i0 = 1.f / l0, i1 = 1.f / l1;
    uint32_t* OH = g_AH + (size_t)(b * SEQ + q0 + wm) * ROWU + h * 32;
    uint32_t* OL = g_AL + (size_t)(b * SEQ + q0 + wm) * ROWU + h * 32;
#pragma unroll
    for (int nt = 0; nt < 8; nt++) {
        const int colu = nt * 4 + tg;
        uint32_t hp, lp;
        split2(o[nt][0] * i0, o[nt][1] * i0, hp, lp);
        OH[(size_t)g * ROWU + colu] = hp;
        OL[(size_t)g * ROWU + colu] = lp;
        split2(o[nt][2] * i1, o[nt][3] * i1, hp, lp);
        OH[(size_t)(g + 8) * ROWU + colu] = hp;
        OL[(size_t)(g + 8) * ROWU + colu] = lp;
    }
}

// ---------------------------------------------------------------------------
// Launch
// ---------------------------------------------------------------------------
extern "C" void kernel_launch(void* const* d_in, const int* in_sizes, int n_in,
                              void* d_out, int out_size)
{
    const float* query = (const float*)d_in[0];
    const float* key_  = (const float*)d_in[1];
    const float* value = (const float*)d_in[2];
    const float* Wq    = (const float*)d_in[3];
    const float* Wk    = (const float*)d_in[4];
    const float* Wv    = (const float*)d_in[5];
    const float* Wo    = (const float*)d_in[6];
    const int*   mask  = (const int*)d_in[7];
    float* out = (float*)d_out;

    uint32_t *qH, *qL, *kH, *kL, *vH, *vL;
    uint32_t *wqH, *wqL, *wkH, *wkL, *wvH, *wvL, *woH, *woL;
    uint32_t *QH, *QL, *KH, *KL, *VH, *VL, *AH, *AL;
    cudaGetSymbolAddress((void**)&qH, g_qH);   cudaGetSymbolAddress((void**)&qL, g_qL);
    cudaGetSymbolAddress((void**)&kH, g_kH);   cudaGetSymbolAddress((void**)&kL, g_kL);
    cudaGetSymbolAddress((void**)&vH, g_vH);   cudaGetSymbolAddress((void**)&vL, g_vL);
    cudaGetSymbolAddress((void**)&wqH, g_wqH); cudaGetSymbolAddress((void**)&wqL, g_wqL);
    cudaGetSymbolAddress((void**)&wkH, g_wkH); cudaGetSymbolAddress((void**)&wkL, g_wkL);
    cudaGetSymbolAddress((void**)&wvH, g_wvH); cudaGetSymbolAddress((void**)&wvL, g_wvL);
    cudaGetSymbolAddress((void**)&woH, g_woH); cudaGetSymbolAddress((void**)&woL, g_woL);
    cudaGetSymbolAddress((void**)&QH, g_QH);   cudaGetSymbolAddress((void**)&QL, g_QL);
    cudaGetSymbolAddress((void**)&KH, g_KH);   cudaGetSymbolAddress((void**)&KL, g_KL);
    cudaGetSymbolAddress((void**)&VH, g_VH);   cudaGetSymbolAddress((void**)&VL, g_VL);
    cudaGetSymbolAddress((void**)&AH, g_AH);   cudaGetSymbolAddress((void**)&AL, g_AL);

    // 1) One-time splits of inputs and weights
    const int n4big = MROWS * DM / 4;   // 1048576
    const int n4w   = DM * DM / 4;      // 65536
    convert_split<<<n4big / 256, 256>>>(query, qH, qL, n4big);
    convert_split<<<n4big / 256, 256>>>(key_,  kH, kL, n4big);
    convert_split<<<n4big / 256, 256>>>(value, vH, vL, n4big);
    convert_split<<<n4w / 256, 256>>>(Wq, wqH, wqL, n4w);
    convert_split<<<n4w / 256, 256>>>(Wk, wkH, wkL, n4w);
    convert_split<<<n4w / 256, 256>>>(Wv, wvH, wvL, n4w);
    convert_split<<<n4w / 256, 256>>>(Wo, woH, woL, n4w);

    // 2) Projections (split outputs for flash)
    dim3 gGrid(DM / 64, MROWS / 128);   // (8, 64)
    gemm_pre<true><<<gGrid, 256>>>(qH, qL, wqH, wqL, nullptr, QH, QL);
    gemm_pre<true><<<gGrid, 256>>>(kH, kL, wkH, wkL, nullptr, KH, KL);
    gemm_pre<true><<<gGrid, 256>>>(vH, vL, wvH, wvL, nullptr, VH, VL);

    // 3) Flash attention
    cudaFuncSetAttribute(flash_bf3,
                         cudaFuncAttributeMaxDynamicSharedMemorySize, SM_U32 * 4);
    dim3 fGrid(SEQ / 128, NH, B_);
    flash_bf3<<<fGrid, 256, SM_U32 * 4>>>(mask);

    // 4) Output projection (f32 out)
    gemm_pre<false><<<gGrid, 256>>>(AH, AL, woH, woL, out, nullptr, nullptr);
}

// round 8
// speedup vs baseline: 2.8340x; 1.1723x over previous
#include <cuda_runtime.h>
#include <cuda_bf16.h>
#include <cstdint>

// Problem constants
#define B_   4
#define SEQ  2048
#define DM   512
#define NH   8
#define HD   64
#define MROWS (B_ * SEQ)     // 8192
#define ROWU  (DM / 2)       // 256 u32 (bf16 pairs) per row

// ---------------------------------------------------------------------------
// Persistent bf16 hi/lo planes (u32 = packed bf16x2 pair (2i, 2i+1))
// ---------------------------------------------------------------------------
__device__ uint32_t g_qH[MROWS * ROWU], g_qL[MROWS * ROWU];
__device__ uint32_t g_kH[MROWS * ROWU], g_kL[MROWS * ROWU];
__device__ uint32_t g_vH[MROWS * ROWU], g_vL[MROWS * ROWU];
__device__ uint32_t g_wqH[DM * ROWU], g_wqL[DM * ROWU];
__device__ uint32_t g_wkH[DM * ROWU], g_wkL[DM * ROWU];
__device__ uint32_t g_wvH[DM * ROWU], g_wvL[DM * ROWU];
__device__ uint32_t g_woH[DM * ROWU], g_woL[DM * ROWU];
__device__ uint32_t g_QH[MROWS * ROWU], g_QL[MROWS * ROWU];
__device__ uint32_t g_KH[MROWS * ROWU], g_KL[MROWS * ROWU];
__device__ uint32_t g_VH[MROWS * ROWU], g_VL[MROWS * ROWU];
__device__ uint32_t g_AH[MROWS * ROWU], g_AL[MROWS * ROWU];

// ---------------------------------------------------------------------------
// Helpers
// ---------------------------------------------------------------------------
__device__ __forceinline__ void split2(float x0, float x1,
                                       uint32_t& hp, uint32_t& lp) {
    float h0 = __bfloat162float(__float2bfloat16_rn(x0));
    float h1 = __bfloat162float(__float2bfloat16_rn(x1));
    asm("cvt.rn.bf16x2.f32 %0, %1, %2;" : "=r"(hp) : "f"(h1), "f"(h0));
    asm("cvt.rn.bf16x2.f32 %0, %1, %2;" : "=r"(lp) : "f"(x1 - h1), "f"(x0 - h0));
}

__device__ __forceinline__ float ex2(float x) {
    float y;
    asm("ex2.approx.ftz.f32 %0, %1;" : "=f"(y) : "f"(x));
    return y;
}

__device__ __forceinline__ void mmabf(float* d, const uint32_t* a, const uint32_t* b) {
    asm volatile(
        "mma.sync.aligned.m16n8k16.row.col.f32.bf16.bf16.f32 "
        "{%0,%1,%2,%3}, {%4,%5,%6,%7}, {%8,%9}, {%0,%1,%2,%3};"
        : "+f"(d[0]), "+f"(d[1]), "+f"(d[2]), "+f"(d[3])
        : "r"(a[0]), "r"(a[1]), "r"(a[2]), "r"(a[3]), "r"(b[0]), "r"(b[1]));
}

__device__ __forceinline__ void ldsm4(uint32_t* r, uint32_t addr) {
    asm volatile("ldmatrix.sync.aligned.m8n8.x4.shared.b16 {%0,%1,%2,%3}, [%4];"
                 : "=r"(r[0]), "=r"(r[1]), "=r"(r[2]), "=r"(r[3]) : "r"(addr));
}
__device__ __forceinline__ void ldsm4t(uint32_t* r, uint32_t addr) {
    asm volatile("ldmatrix.sync.aligned.m8n8.x4.trans.shared.b16 {%0,%1,%2,%3}, [%4];"
                 : "=r"(r[0]), "=r"(r[1]), "=r"(r[2]), "=r"(r[3]) : "r"(addr));
}
__device__ __forceinline__ void cpasync16(uint32_t dst_smem, const void* src) {
    asm volatile("cp.async.cg.shared.global [%0], [%1], 16;"
                 :: "r"(dst_smem), "l"(src));
}

// ---------------------------------------------------------------------------
// Convert: f32 -> hi/lo bf16 planes
// ---------------------------------------------------------------------------
__global__ __launch_bounds__(256) void convert_split(
    const float* __restrict__ src, uint32_t* __restrict__ dh,
    uint32_t* __restrict__ dl, int n4)
{
    int i = blockIdx.x * 256 + threadIdx.x;
    if (i >= n4) return;
    float4 v = ((const float4*)src)[i];
    uint32_t h0, l0, h1, l1;
    split2(v.x, v.y, h0, l0);
    split2(v.z, v.w, h1, l1);
    ((uint2*)dh)[i] = make_uint2(h0, h1);
    ((uint2*)dl)[i] = make_uint2(l0, l1);
}

// ---------------------------------------------------------------------------
// Projection GEMM body: C = A[M,512] * W[512,512]^T, bf16x3, pre-split.
// 128x64 tile, BK=32, 3-stage cp.async ring, 1 barrier/step, term-major MMAs.
// smem per stage (u32): AH[128*20] AL[128*20] WH[64*20] WL[64*20] = 7680
// ---------------------------------------------------------------------------
#define G_STG 7680
#define G_AH 0
#define G_AL 2560
#define G_WH 5120
#define G_WL 6400

template <bool SPLIT_OUT>
__device__ __forceinline__ void gemm_body(
    const uint32_t* __restrict__ AH, const uint32_t* __restrict__ AL,
    const uint32_t* __restrict__ WH, const uint32_t* __restrict__ WL,
    float* __restrict__ C, uint32_t* __restrict__ CH, uint32_t* __restrict__ CL)
{
    extern __shared__ uint32_t gsm[];
    const int tid = threadIdx.x, lane = tid & 31, warp = tid >> 5;
    const int g = lane >> 2, tg = lane & 3;
    const int mat = lane >> 3, l7 = lane & 7;
    const int m0 = blockIdx.y * 128, n0 = blockIdx.x * 64;
    const int wm = (warp >> 1) * 32, wn = (warp & 1) * 32;

    const uint32_t sb = (uint32_t)__cvta_generic_to_shared(gsm);
    const int rowA = (mat & 1) * 8 + l7, colA = (mat >> 1) * 4;
    const int rowW = (mat >> 1) * 8 + l7, colW = (mat & 1) * 4;
    const uint32_t oAH = 4 * (G_AH + (wm + rowA) * 20 + colA);
    const uint32_t oAL = 4 * (G_AL + (wm + rowA) * 20 + colA);
    const uint32_t oWH = 4 * (G_WH + (wn + rowW) * 20 + colW);
    const uint32_t oWL = 4 * (G_WL + (wn + rowW) * 20 + colW);

    float acc[2][4][4];
#pragma unroll
    for (int mt = 0; mt < 2; mt++)
#pragma unroll
        for (int nt = 0; nt < 4; nt++)
#pragma unroll
            for (int j = 0; j < 4; j++) acc[mt][nt][j] = 0.f;

    // Staging: rr = tid>>2 (0..63), ch = (tid&3)*4 u32
    const int rr = tid >> 2, ch = (tid & 3) * 4;
    const uint32_t* sA0h = AH + (size_t)(m0 + rr) * ROWU + ch;
    const uint32_t* sA1h = AH + (size_t)(m0 + rr + 64) * ROWU + ch;
    const uint32_t* sA0l = AL + (size_t)(m0 + rr) * ROWU + ch;
    const uint32_t* sA1l = AL + (size_t)(m0 + rr + 64) * ROWU + ch;
    const uint32_t* sWh  = WH + (size_t)(n0 + rr) * ROWU + ch;
    const uint32_t* sWl  = WL + (size_t)(n0 + rr) * ROWU + ch;
    const uint32_t dA0 = rr * 20 + ch, dA1 = (rr + 64) * 20 + ch, dW = rr * 20 + ch;

#define GSTAGE(s, buf)                                                  \
    {                                                                   \
        const uint32_t b4 = sb + 4 * ((buf) * G_STG);                   \
        const int ku = (s) * 16;                                        \
        cpasync16(b4 + 4 * (G_AH + dA0), sA0h + ku);                    \
        cpasync16(b4 + 4 * (G_AH + dA1), sA1h + ku);                    \
        cpasync16(b4 + 4 * (G_AL + dA0), sA0l + ku);                    \
        cpasync16(b4 + 4 * (G_AL + dA1), sA1l + ku);                    \
        cpasync16(b4 + 4 * (G_WH + dW),  sWh + ku);                     \
        cpasync16(b4 + 4 * (G_WL + dW),  sWl + ku);                     \
        asm volatile("cp.async.commit_group;");                         \
    }

    GSTAGE(0, 0);
    GSTAGE(1, 1);

    for (int s = 0; s < 16; s++) {
        if (s < 15) asm volatile("cp.async.wait_group 1;");
        else        asm volatile("cp.async.wait_group 0;");
        __syncthreads();
        if (s + 2 < 16) GSTAGE(s + 2, (s + 2) % 3);
        const uint32_t bo = sb + 4 * ((s % 3) * G_STG);
#pragma unroll
        for (int kc = 0; kc < 2; kc++) {
            uint32_t ah[2][4], al[2][4], bh[2][4], bl[2][4];
            ldsm4(ah[0], bo + oAH + 4 * (kc * 8));
            ldsm4(ah[1], bo + oAH + 4 * (16 * 20 + kc * 8));
            ldsm4(al[0], bo + oAL + 4 * (kc * 8));
            ldsm4(al[1], bo + oAL + 4 * (16 * 20 + kc * 8));
            ldsm4(bh[0], bo + oWH + 4 * (kc * 8));
            ldsm4(bh[1], bo + oWH + 4 * (16 * 20 + kc * 8));
            ldsm4(bl[0], bo + oWL + 4 * (kc * 8));
            ldsm4(bl[1], bo + oWL + 4 * (16 * 20 + kc * 8));
            // term 1: ah*bh over all 8 accumulators
#pragma unroll
            for (int mt = 0; mt < 2; mt++)
#pragma unroll
                for (int np = 0; np < 2; np++) {
                    mmabf(acc[mt][2 * np],     ah[mt], bh[np]);
                    mmabf(acc[mt][2 * np + 1], ah[mt], bh[np] + 2);
                }
            // term 2: ah*bl
#pragma unroll
            for (int mt = 0; mt < 2; mt++)
#pragma unroll
                for (int np = 0; np < 2; np++) {
                    mmabf(acc[mt][2 * np],     ah[mt], bl[np]);
                    mmabf(acc[mt][2 * np + 1], ah[mt], bl[np] + 2);
                }
            // term 3: al*bh
#pragma unroll
            for (int mt = 0; mt < 2; mt++)
#pragma unroll
                for (int np = 0; np < 2; np++) {
                    mmabf(acc[mt][2 * np],     al[mt], bh[np]);
                    mmabf(acc[mt][2 * np + 1], al[mt], bh[np] + 2);
                }
        }
    }

#pragma unroll
    for (int mt = 0; mt < 2; mt++)
#pragma unroll
        for (int nt = 0; nt < 4; nt++) {
            const int row = m0 + wm + mt * 16 + g;
            if (SPLIT_OUT) {
                const int colu = (n0 + wn) / 2 + nt * 4 + tg;
                uint32_t hp, lp;
                split2(acc[mt][nt][0], acc[mt][nt][1], hp, lp);
                CH[(size_t)row * ROWU + colu] = hp;
                CL[(size_t)row * ROWU + colu] = lp;
                split2(acc[mt][nt][2], acc[mt][nt][3], hp, lp);
                CH[(size_t)(row + 8) * ROWU + colu] = hp;
                CL[(size_t)(row + 8) * ROWU + colu] = lp;
            } else {
                const int col = n0 + wn + nt * 8 + 2 * tg;
                float2 lo = {acc[mt][nt][0], acc[mt][nt][1]};
                float2 hi = {acc[mt][nt][2], acc[mt][nt][3]};
                *(float2*)&C[(size_t)row * DM + col] = lo;
                *(float2*)&C[(size_t)(row + 8) * DM + col] = hi;
            }
        }
#undef GSTAGE
}

struct GT { const uint32_t *AH, *AL, *WH, *WL; uint32_t *CH, *CL; };

__global__ __launch_bounds__(256, 2) void gemm_qkv(GT t0, GT t1, GT t2)
{
    const GT& t = (blockIdx.z == 0) ? t0 : (blockIdx.z == 1) ? t1 : t2;
    gemm_body<true>(t.AH, t.AL, t.WH, t.WL, nullptr, t.CH, t.CL);
}

__global__ __launch_bounds__(256, 2) void gemm_out(
    const uint32_t* __restrict__ AH, const uint32_t* __restrict__ AL,
    const uint32_t* __restrict__ WH, const uint32_t* __restrict__ WL,
    float* __restrict__ C)
{
    gemm_body<false>(AH, AL, WH, WL, C, nullptr, nullptr);
}

// ---------------------------------------------------------------------------
// Flash attention: bf16x3, register P, 3-stage cp.async ring (1 barrier/tile),
// bf16 mask-bias, rescale-skip vote, deferred l reduction.
// smem (u32): 3 x [KH|KL|VH|VL](64 x 36) + bias[1024]
// ---------------------------------------------------------------------------
#define ST 36
#define PLANE (64 * ST)          // 2304
#define FBUF (4 * PLANE)         // 9216
#define OFF_BIAS (3 * FBUF)      // 27648
#define FSM_U32 (OFF_BIAS + SEQ / 2)   // 28672 u32 = 114688 B

extern __shared__ uint32_t fa_smem[];

__global__ __launch_bounds__(256, 2) void flash_bf3(const int* __restrict__ mask)
{
    const int tid = threadIdx.x, lane = tid & 31, warp = tid >> 5;
    const int g = lane >> 2, tg = lane & 3;
    const int mat = lane >> 3, l7 = lane & 7;
    const int q0 = blockIdx.x * 128, h = blockIdx.y, b = blockIdx.z;
    const int wm = warp * 16;
    const float cs = 0.125f * 1.44269504f;

    uint32_t* Bs = fa_smem + OFF_BIAS;
    const uint32_t sbase = (uint32_t)__cvta_generic_to_shared(fa_smem);
    const uint32_t loK = 4 * (((mat >> 1) * 8 + l7) * ST + (mat & 1) * 4);
    const uint32_t loV = 4 * (((mat & 1) * 8 + l7) * ST + (mat >> 1) * 4);

    // Mask -> bf16 bias plane (0 or -1e30), once per CTA
    {
        const int2* mrow = (const int2*)(mask + b * SEQ);
#pragma unroll
        for (int i = tid; i < SEQ / 2; i += 256) {
            int2 mv = mrow[i];
            float b0 = mv.x ? 0.f : -1.0e30f;
            float b1 = mv.y ? 0.f : -1.0e30f;
            uint32_t bp;
            asm("cvt.rn.bf16x2.f32 %0, %1, %2;" : "=r"(bp) : "f"(b1), "f"(b0));
            Bs[i] = bp;
        }
    }

    // Q fragments from pre-split planes
    uint32_t qh[4][4], ql[4][4];
    {
        const uint32_t* QHp = g_QH + (size_t)(b * SEQ + q0 + wm) * ROWU + h * 32;
        const uint32_t* QLp = g_QL + (size_t)(b * SEQ + q0 + wm) * ROWU + h * 32;
#pragma unroll
        for (int kc = 0; kc < 4; kc++) {
            const int c = kc * 8 + tg;
            qh[kc][0] = QHp[(size_t)g * ROWU + c];
            qh[kc][1] = QHp[(size_t)(g + 8) * ROWU + c];
            qh[kc][2] = QHp[(size_t)g * ROWU + c + 4];
            qh[kc][3] = QHp[(size_t)(g + 8) * ROWU + c + 4];
            ql[kc][0] = QLp[(size_t)g * ROWU + c];
            ql[kc][1] = QLp[(size_t)(g + 8) * ROWU + c];
            ql[kc][2] = QLp[(size_t)g * ROWU + c + 4];
            ql[kc][3] = QLp[(size_t)(g + 8) * ROWU + c + 4];
        }
    }

    // cp.async staging map
    const int pl = tid >> 6, sIn = tid & 63;
    const int rB = sIn >> 3, qc = (sIn & 7) * 4;
    const uint32_t* sp = (pl == 0) ? g_KH : (pl == 1) ? g_KL : (pl == 2) ? g_VH : g_VL;
    sp += (size_t)(b * SEQ) * ROWU + h * 32 + qc;
    const uint32_t dbase = pl * PLANE + rB * ST + qc;

#define STAGE(kv0, buf)                                                        \
    {                                                                          \
        const uint32_t d0 = sbase + 4 * ((buf) * FBUF + dbase);                \
        const uint32_t* s0 = sp + (size_t)(kv0 + rB) * ROWU;                   \
        _Pragma("unroll")                                                      \
        for (int u = 0; u < 8; u++)                                            \
            cpasync16(d0 + 4 * (u * 8 * ST), s0 + (size_t)(u * 8) * ROWU);     \
        asm volatile("cp.async.commit_group;");                                \
    }

    STAGE(0, 0);
    STAGE(64, 1);

    float o[8][4];
#pragma unroll
    for (int nt = 0; nt < 8; nt++)
#pragma unroll
        for (int j = 0; j < 4; j++) o[nt][j] = 0.f;
    float m0r = -3.0e38f, m1r = -3.0e38f, l0 = 0.f, l1 = 0.f;

    for (int t = 0; t < 32; t++) {
        if (t < 31) asm volatile("cp.async.wait_group 1;");
        else        asm volatile("cp.async.wait_group 0;");
        __syncthreads();   // tile t ready; t-1 compute finished everywhere
        if (t + 2 < 32) STAGE((t + 2) * 64, (t + 2) % 3);

        const uint32_t bb = sbase + 4 * ((t % 3) * FBUF);
        const uint32_t aKH = bb + loK,                aKL = bb + 4 * PLANE + loK;
        const uint32_t aVH = bb + 8 * PLANE + loV,    aVL = bb + 12 * PLANE + loV;
        const int kv0 = t * 64;

        // S = Q K^T
        float s[8][4];
#pragma unroll
        for (int nt = 0; nt < 8; nt++)
#pragma unroll
            for (int j = 0; j < 4; j++) s[nt][j] = 0.f;
#pragma unroll
        for (int ntp = 0; ntp < 4; ntp++) {
#pragma unroll
            for (int kc = 0; kc < 4; kc++) {
                uint32_t bh[4], bl[4];
                ldsm4(bh, aKH + 4 * (ntp * 16 * ST + kc * 8));
                ldsm4(bl, aKL + 4 * (ntp * 16 * ST + kc * 8));
                mmabf(s[2 * ntp],     qh[kc], bh);
                mmabf(s[2 * ntp + 1], qh[kc], bh + 2);
                mmabf(s[2 * ntp],     qh[kc], bl);
                mmabf(s[2 * ntp + 1], qh[kc], bl + 2);
                mmabf(s[2 * ntp],     ql[kc], bh);
                mmabf(s[2 * ntp + 1], ql[kc], bh + 2);
            }
        }

        // Additive mask bias (0 or ~-1e30; exp underflows to exactly 0)
#pragma unroll
        for (int nt = 0; nt < 8; nt++) {
            uint32_t bp = Bs[(kv0 >> 1) + nt * 4 + tg];
            float bb0 = __uint_as_float(bp << 16);
            float bb1 = __uint_as_float(bp & 0xFFFF0000u);
            s[nt][0] += bb0; s[nt][1] += bb1;
            s[nt][2] += bb0; s[nt][3] += bb1;
        }

        // Online softmax
        float mx0 = -3.0e38f, mx1 = -3.0e38f;
#pragma unroll
        for (int nt = 0; nt < 8; nt++) {
            mx0 = fmaxf(mx0, fmaxf(s[nt][0], s[nt][1]));
            mx1 = fmaxf(mx1, fmaxf(s[nt][2], s[nt][3]));
        }
        mx0 = fmaxf(mx0, __shfl_xor_sync(0xffffffffu, mx0, 1));
        mx0 = fmaxf(mx0, __shfl_xor_sync(0xffffffffu, mx0, 2));
        mx1 = fmaxf(mx1, __shfl_xor_sync(0xffffffffu, mx1, 1));
        mx1 = fmaxf(mx1, __shfl_xor_sync(0xffffffffu, mx1, 2));

        const float mn0 = fmaxf(m0r, mx0), mn1 = fmaxf(m1r, mx1);
        bool chg = (mn0 > m0r) || (mn1 > m1r);
        if (__any_sync(0xffffffffu, chg)) {
            const float al0 = ex2((m0r - mn0) * cs), al1 = ex2((m1r - mn1) * cs);
            l0 *= al0; l1 *= al1;
#pragma unroll
            for (int nt = 0; nt < 8; nt++) {
                o[nt][0] *= al0; o[nt][1] *= al0;
                o[nt][2] *= al1; o[nt][3] *= al1;
            }
        }
        m0r = mn0; m1r = mn1;

        float sm0 = 0.f, sm1 = 0.f;
#pragma unroll
        for (int nt = 0; nt < 8; nt++) {
            s[nt][0] = ex2((s[nt][0] - mn0) * cs);
            s[nt][1] = ex2((s[nt][1] - mn0) * cs);
            s[nt][2] = ex2((s[nt][2] - mn1) * cs);
            s[nt][3] = ex2((s[nt][3] - mn1) * cs);
            sm0 += s[nt][0] + s[nt][1];
            sm1 += s[nt][2] + s[nt][3];
        }
        l0 += sm0;   // lane-partial; reduced once at the end
        l1 += sm1;

        // Pack P into hi/lo A-fragments
        uint32_t pah[4][4], pal[4][4];
#pragma unroll
        for (int kc = 0; kc < 4; kc++) {
            split2(s[2 * kc][0],     s[2 * kc][1],     pah[kc][0], pal[kc][0]);
            split2(s[2 * kc][2],     s[2 * kc][3],     pah[kc][1], pal[kc][1]);
            split2(s[2 * kc + 1][0], s[2 * kc + 1][1], pah[kc][2], pal[kc][2]);
            split2(s[2 * kc + 1][2], s[2 * kc + 1][3], pah[kc][3], pal[kc][3]);
        }

        // O += P V
#pragma unroll
        for (int ntp = 0; ntp < 4; ntp++) {
#pragma unroll
            for (int kc = 0; kc < 4; kc++) {
                uint32_t vh[4], vl[4];
                ldsm4t(vh, aVH + 4 * (kc * 16 * ST + ntp * 8));
                ldsm4t(vl, aVL + 4 * (kc * 16 * ST + ntp * 8));
                mmabf(o[2 * ntp],     pah[kc], vh);
                mmabf(o[2 * ntp + 1], pah[kc], vh + 2);
                mmabf(o[2 * ntp],     pah[kc], vl);
                mmabf(o[2 * ntp + 1], pah[kc], vl + 2);
                mmabf(o[2 * ntp],     pal[kc], vh);
                mmabf(o[2 * ntp + 1], pal[kc], vh + 2);
            }
        }
    }

    // Final l reduction + store split Av planes
    l0 += __shfl_xor_sync(0xffffffffu, l0, 1);
    l0 += __shfl_xor_sync(0xffffffffu, l0, 2);
    l1 += __shfl_xor_sync(0xffffffffu, l1, 1);
    l1 += __shfl_xor_sync(0xffffffffu, l1, 2);
    const float i0 = 1.f / l0, i1 = 1.f / l1;
    uint32_t* OH = g_AH + (size_t)(b * SEQ + q0 + wm) * ROWU + h * 32;
    uint32_t* OL = g_AL + (size_t)(b * SEQ + q0 + wm) * ROWU + h * 32;
#pragma unroll
    for (int nt = 0; nt < 8; nt++) {
        const int colu = nt * 4 + tg;
        uint32_t hp, lp;
        split2(o[nt][0] * i0, o[nt][1] * i0, hp, lp);
        OH[(size_t)g * ROWU + colu] = hp;
        OL[(size_t)g * ROWU + colu] = lp;
        split2(o[nt][2] * i1, o[nt][3] * i1, hp, lp);
        OH[(size_t)(g + 8) * ROWU + colu] = hp;
        OL[(size_t)(g + 8) * ROWU + colu] = lp;
    }
#undef STAGE
}

// ---------------------------------------------------------------------------
// Launch
// ---------------------------------------------------------------------------
extern "C" void kernel_launch(void* const* d_in, const int* in_sizes, int n_in,
                              void* d_out, int out_size)
{
    const float* query = (const float*)d_in[0];
    const float* key_  = (const float*)d_in[1];
    const float* value = (const float*)d_in[2];
    const float* Wq    = (const float*)d_in[3];
    const float* Wk    = (const float*)d_in[4];
    const float* Wv    = (const float*)d_in[5];
    const float* Wo    = (const float*)d_in[6];
    const int*   mask  = (const int*)d_in[7];
    float* out = (float*)d_out;

    uint32_t *qH, *qL, *kH, *kL, *vH, *vL;
    uint32_t *wqH, *wqL, *wkH, *wkL, *wvH, *wvL, *woH, *woL;
    uint32_t *QH, *QL, *KH, *KL, *VH, *VL, *AH, *AL;
    cudaGetSymbolAddress((void**)&qH, g_qH);   cudaGetSymbolAddress((void**)&qL, g_qL);
    cudaGetSymbolAddress((void**)&kH, g_kH);   cudaGetSymbolAddress((void**)&kL, g_kL);
    cudaGetSymbolAddress((void**)&vH, g_vH);   cudaGetSymbolAddress((void**)&vL, g_vL);
    cudaGetSymbolAddress((void**)&wqH, g_wqH); cudaGetSymbolAddress((void**)&wqL, g_wqL);
    cudaGetSymbolAddress((void**)&wkH, g_wkH); cudaGetSymbolAddress((void**)&wkL, g_wkL);
    cudaGetSymbolAddress((void**)&wvH, g_wvH); cudaGetSymbolAddress((void**)&wvL, g_wvL);
    cudaGetSymbolAddress((void**)&woH, g_woH); cudaGetSymbolAddress((void**)&woL, g_woL);
    cudaGetSymbolAddress((void**)&QH, g_QH);   cudaGetSymbolAddress((void**)&QL, g_QL);
    cudaGetSymbolAddress((void**)&KH, g_KH);   cudaGetSymbolAddress((void**)&KL, g_KL);
    cudaGetSymbolAddress((void**)&VH, g_VH);   cudaGetSymbolAddress((void**)&VL, g_VL);
    cudaGetSymbolAddress((void**)&AH, g_AH);   cudaGetSymbolAddress((void**)&AL, g_AL);

    // 1) One-time splits
    const int n4big = MROWS * DM / 4;
    const int n4w   = DM * DM / 4;
    convert_split<<<n4big / 256, 256>>>(query, qH, qL, n4big);
    convert_split<<<n4big / 256, 256>>>(key_,  kH, kL, n4big);
    convert_split<<<n4big / 256, 256>>>(value, vH, vL, n4big);
    convert_split<<<n4w / 256, 256>>>(Wq, wqH, wqL, n4w);
    convert_split<<<n4w / 256, 256>>>(Wk, wkH, wkL, n4w);
    convert_split<<<n4w / 256, 256>>>(Wv, wvH, wvL, n4w);
    convert_split<<<n4w / 256, 256>>>(Wo, woH, woL, n4w);

    const int gemm_smem = G_STG * 3 * 4;       // 92160 B
    const int flash_smem = FSM_U32 * 4;        // 114688 B
    cudaFuncSetAttribute(gemm_qkv, cudaFuncAttributeMaxDynamicSharedMemorySize, gemm_smem);
    cudaFuncSetAttribute(gemm_out, cudaFuncAttributeMaxDynamicSharedMemorySize, gemm_smem);
    cudaFuncSetAttribute(flash_bf3, cudaFuncAttributeMaxDynamicSharedMemorySize, flash_smem);

    // 2) Q/K/V projections fused into one launch (grid.z = which)
    GT tq = {qH, qL, wqH, wqL, QH, QL};
    GT tk = {kH, kL, wkH, wkL, KH, KL};
    GT tv = {vH, vL, wvH, wvL, VH, VL};
    dim3 gGrid(DM / 64, MROWS / 128, 3);   // (8, 64, 3)
    gemm_qkv<<<gGrid, 256, gemm_smem>>>(tq, tk, tv);

    // 3) Flash attention
    dim3 fGrid(SEQ / 128, NH, B_);
    flash_bf3<<<fGrid, 256, flash_smem>>>(mask);

    // 4) Output projection
    dim3 oGrid(DM / 64, MROWS / 128, 1);
    gemm_out<<<oGrid, 256, gemm_smem>>>(AH, AL, woH, woL, out);
}